// round 9
// baseline (speedup 1.0000x reference)
#include <cuda_runtime.h>
#include <cuda_bf16.h>
#include <stdint.h>

#define N_POINTS 262144
#define SP_FEAT  128
#define HIDDEN   64
#define EMBED    256
#define NUM_SP   4096
#define NUM_SP2  256
#define PAD_LIMIT 64
#define TILE_M   128
#define N_TILES  (N_POINTS / TILE_M)   // 2048
#define GRID_MAIN 148

// ---------------- device scratch ----------------
__device__ int g_tok[NUM_SP * EMBED];          // float bits, values >= 0
__device__ int g_mask_is_i32;
// prepacked B fragments (mma.m16n8k16 layout), uint4 = {hi_reg0, hi_reg1, lo_reg0, lo_reg1}
__device__ __align__(16) uint4 g_w1f[8 * 8 * 32];    // [n8][ks][lane] (8 KB)
__device__ __align__(16) uint4 g_w2f[32 * 4 * 32];   // [n8][ks][lane] (64 KB)

// ---------------- helpers ----------------
__device__ __forceinline__ uint32_t smem_u32(const void* p) {
    uint32_t a;
    asm("{ .reg .u64 t; cvta.to.shared.u64 t, %1; cvt.u32.u64 %0, t; }" : "=r"(a) : "l"(p));
    return a;
}
__device__ __forceinline__ uint32_t off256(uint32_t row, uint32_t k) {
    return row * 256u + (((k >> 3) ^ (row & 7u)) << 4) + (k & 7u) * 2u;
}
__device__ __forceinline__ uint32_t off128(uint32_t row, uint32_t k) {
    return row * 128u + ((((k >> 3) ^ (row & 7u)) & 7u) << 4) + (k & 7u) * 2u;
}
__device__ __forceinline__ uint32_t pack_bf2(float a, float b) {
    __nv_bfloat162 t = __floats2bfloat162_rn(a, b);
    return *(uint32_t*)&t;
}
__device__ __forceinline__ void ldsm4(uint32_t r[4], uint32_t addr) {
    asm volatile("ldmatrix.sync.aligned.m8n8.x4.shared.b16 {%0,%1,%2,%3}, [%4];"
                 : "=r"(r[0]), "=r"(r[1]), "=r"(r[2]), "=r"(r[3]) : "r"(addr));
}
__device__ __forceinline__ void mma_bf16(float c[4], const uint32_t a[4],
                                         uint32_t b0, uint32_t b1) {
    asm volatile("mma.sync.aligned.m16n8k16.row.col.f32.bf16.bf16.f32 "
                 "{%0,%1,%2,%3}, {%4,%5,%6,%7}, {%8,%9}, {%0,%1,%2,%3};"
                 : "+f"(c[0]), "+f"(c[1]), "+f"(c[2]), "+f"(c[3])
                 : "r"(a[0]), "r"(a[1]), "r"(a[2]), "r"(a[3]), "r"(b0), "r"(b1));
}
__device__ __forceinline__ void cp_async16(uint32_t dst, const void* src) {
    asm volatile("cp.async.cg.shared.global [%0], [%1], 16;" :: "r"(dst), "l"(src));
}
#define CP_COMMIT() asm volatile("cp.async.commit_group;" ::: "memory")
#define CP_WAIT0()  asm volatile("cp.async.wait_group 0;"  ::: "memory")

// warp butterfly max over lanes differing in bits 2..4 (q-group of 8 lanes)
__device__ __forceinline__ float qgroup_max(float v) {
    v = fmaxf(v, __shfl_xor_sync(0xFFFFFFFFu, v, 4));
    v = fmaxf(v, __shfl_xor_sync(0xFFFFFFFFu, v, 8));
    v = fmaxf(v, __shfl_xor_sync(0xFFFFFFFFu, v, 16));
    return v;
}

// ---------------- smem layout (dynamic) ----------------
#define S_XSTAGE 0          // 128x128 f32 staging (65536)
#define S_XHI    65536      // 128x128 bf16, 256B rows, swizzled (32768)
#define S_XLO    98304
#define S_HHI    131072     // 128x64 bf16, 128B rows, swizzled (16384)
#define S_HLO    147456
#define S_SPS    163840     // 128 ints
#define S_B1     164352     // 64 f32
#define S_B2     164608     // 256 f32
#define SMEM_TOTAL 165632

// ---------------- prep kernel ----------------
__global__ void k_prep_w(const float* __restrict__ W1, const float* __restrict__ W2,
                         const int* __restrict__ msk) {
    int i = blockIdx.x * blockDim.x + threadIdx.x;     // 8192 threads
    if (blockIdx.x == 0) {
        __shared__ int bad;
        if (threadIdx.x == 0) bad = 0;
        __syncthreads();
        for (int j = threadIdx.x; j < 1024; j += blockDim.x)
            if ((unsigned)msk[j] > 1u) atomicOr(&bad, 1);
        __syncthreads();
        if (threadIdx.x == 0) g_mask_is_i32 = bad ? 0 : 1;
    }
    if (i < 2048) {                                     // layer1: [n8(8)][ks(8)][lane]
        int lane = i & 31, ks = (i >> 5) & 7, n8 = i >> 8;
        int n  = 8 * n8 + (lane >> 2);
        int k0 = 16 * ks + 2 * (lane & 3);
        float v00 = W1[k0 * HIDDEN + n],       v01 = W1[(k0 + 1) * HIDDEN + n];
        float v10 = W1[(k0 + 8) * HIDDEN + n], v11 = W1[(k0 + 9) * HIDDEN + n];
        __nv_bfloat16 h00 = __float2bfloat16_rn(v00), h01 = __float2bfloat16_rn(v01);
        __nv_bfloat16 h10 = __float2bfloat16_rn(v10), h11 = __float2bfloat16_rn(v11);
        uint4 f;
        f.x = pack_bf2(v00, v01);
        f.y = pack_bf2(v10, v11);
        f.z = pack_bf2(v00 - __bfloat162float(h00), v01 - __bfloat162float(h01));
        f.w = pack_bf2(v10 - __bfloat162float(h10), v11 - __bfloat162float(h11));
        g_w1f[i] = f;
    } else if (i < 2048 + 4096) {                       // layer2: [n8(32)][ks(4)][lane]
        int j = i - 2048;
        int lane = j & 31, ks = (j >> 5) & 3, n8 = j >> 7;
        int n  = 8 * n8 + (lane >> 2);
        int k0 = 16 * ks + 2 * (lane & 3);
        float v00 = W2[k0 * EMBED + n],       v01 = W2[(k0 + 1) * EMBED + n];
        float v10 = W2[(k0 + 8) * EMBED + n], v11 = W2[(k0 + 9) * EMBED + n];
        __nv_bfloat16 h00 = __float2bfloat16_rn(v00), h01 = __float2bfloat16_rn(v01);
        __nv_bfloat16 h10 = __float2bfloat16_rn(v10), h11 = __float2bfloat16_rn(v11);
        uint4 f;
        f.x = pack_bf2(v00, v01);
        f.y = pack_bf2(v10, v11);
        f.z = pack_bf2(v00 - __bfloat162float(h00), v01 - __bfloat162float(h01));
        f.w = pack_bf2(v10 - __bfloat162float(h10), v11 - __bfloat162float(h11));
        g_w2f[j] = f;
    }
}

// ---------------- persistent main kernel ----------------
// warp = (wm 0..7, wn 0..1): rows 16wm..+15; layer1 cols 32wn..+31; layer2 cols 128wn..+127
__global__ __launch_bounds__(512, 1)
void k_main(const float* __restrict__ x, const int* __restrict__ idx10,
            const float* __restrict__ b1, const float* __restrict__ b2)
{
    extern __shared__ char sm[];
    const uint32_t smb = smem_u32(sm);
    const int tid  = threadIdx.x;
    const int wid  = tid >> 5;
    const int lane = tid & 31;
    const int wm   = wid & 7;
    const int wn   = wid >> 3;
    const int q    = lane & 3;
    const int rb   = lane >> 2;
    const int arow  = lane & 15;
    const int acol8 = (lane >> 4) * 8;

    if (tid < 64)  ((float*)(sm + S_B1))[tid] = b1[tid];
    if (tid < 256) ((float*)(sm + S_B2))[tid] = b2[tid];

    int t = blockIdx.x;
    {
        const float* src = x + (size_t)t * (TILE_M * 32) * 4;
        #pragma unroll
        for (int j = 0; j < 8; j++) {
            int idx = tid + j * 512;
            cp_async16(smb + S_XSTAGE + idx * 16, src + idx * 4);
        }
    }
    CP_COMMIT();

    for (; t < N_TILES; t += GRID_MAIN) {
        CP_WAIT0();
        __syncthreads();

        if (tid < 128) ((int*)(sm + S_SPS))[tid] = idx10[t * TILE_M + tid];

        // convert staged f32 -> bf16 hi/lo swizzled
        for (int i = tid; i < TILE_M * 32; i += 512) {
            int p = i >> 5, c4 = i & 31;
            int k = c4 * 4;
            float4 v = ((const float4*)(sm + S_XSTAGE))[i];
            __nv_bfloat16 h0 = __float2bfloat16_rn(v.x), h1 = __float2bfloat16_rn(v.y);
            __nv_bfloat16 h2 = __float2bfloat16_rn(v.z), h3 = __float2bfloat16_rn(v.w);
            uint2 hi = make_uint2(pack_bf2(v.x, v.y), pack_bf2(v.z, v.w));
            uint2 lo = make_uint2(pack_bf2(v.x - __bfloat162float(h0), v.y - __bfloat162float(h1)),
                                  pack_bf2(v.z - __bfloat162float(h2), v.w - __bfloat162float(h3)));
            uint32_t off = off256((uint32_t)p, (uint32_t)k);
            *(uint2*)(sm + S_XHI + off) = hi;
            *(uint2*)(sm + S_XLO + off) = lo;
        }
        __syncthreads();

        // prefetch next tile
        {
            int tn = t + GRID_MAIN;
            if (tn < N_TILES) {
                const float* src = x + (size_t)tn * (TILE_M * 32) * 4;
                #pragma unroll
                for (int j = 0; j < 8; j++) {
                    int idx = tid + j * 512;
                    cp_async16(smb + S_XSTAGE + idx * 16, src + idx * 4);
                }
            }
            CP_COMMIT();
        }

        // ================= layer 1 =================
        float acc[4][4];
        #pragma unroll
        for (int nth = 0; nth < 4; nth++)
            #pragma unroll
            for (int j = 0; j < 4; j++) acc[nth][j] = 0.f;

        {
            uint32_t ah[2][4], al[2][4];
            {
                uint32_t o = off256((uint32_t)(16*wm + arow), (uint32_t)acol8);
                ldsm4(ah[0], smb + S_XHI + o);
                ldsm4(al[0], smb + S_XLO + o);
            }
            #pragma unroll
            for (int ks = 0; ks < 8; ks++) {
                const int cur = ks & 1;
                if (ks < 7) {
                    uint32_t o = off256((uint32_t)(16*wm + arow),
                                        (uint32_t)(16*(ks + 1) + acol8));
                    ldsm4(ah[cur ^ 1], smb + S_XHI + o);
                    ldsm4(al[cur ^ 1], smb + S_XLO + o);
                }
                #pragma unroll
                for (int nth = 0; nth < 4; nth++) {
                    const uint4 f = __ldg(&g_w1f[((4*wn + nth)*8 + ks)*32 + lane]);
                    mma_bf16(acc[nth], ah[cur], f.x, f.y);
                    mma_bf16(acc[nth], al[cur], f.x, f.y);
                    mma_bf16(acc[nth], ah[cur], f.z, f.w);
                }
            }
        }

        // epilogue 1: bias + relu -> bf16 hi/lo into smem H
        {
            const float* b1s = (const float*)(sm + S_B1);
            #pragma unroll
            for (int nth = 0; nth < 4; nth++) {
                const int col = 32*wn + 8*nth + 2*q;
                const float bia0 = b1s[col], bia1 = b1s[col + 1];
                int r1 = 16*wm + rb, r2 = r1 + 8;
                float v00 = fmaxf(acc[nth][0] + bia0, 0.f);
                float v01 = fmaxf(acc[nth][1] + bia1, 0.f);
                float v10 = fmaxf(acc[nth][2] + bia0, 0.f);
                float v11 = fmaxf(acc[nth][3] + bia1, 0.f);
                __nv_bfloat16 h00 = __float2bfloat16_rn(v00), h01 = __float2bfloat16_rn(v01);
                __nv_bfloat16 h10 = __float2bfloat16_rn(v10), h11 = __float2bfloat16_rn(v11);
                uint32_t o1 = off128((uint32_t)r1, (uint32_t)col);
                uint32_t o2 = off128((uint32_t)r2, (uint32_t)col);
                *(uint32_t*)(sm + S_HHI + o1) = pack_bf2(v00, v01);
                *(uint32_t*)(sm + S_HHI + o2) = pack_bf2(v10, v11);
                *(uint32_t*)(sm + S_HLO + o1) = pack_bf2(v00 - __bfloat162float(h00),
                                                         v01 - __bfloat162float(h01));
                *(uint32_t*)(sm + S_HLO + o2) = pack_bf2(v10 - __bfloat162float(h10),
                                                         v11 - __bfloat162float(h11));
            }
        }
        __syncthreads();

        // segment info for this warp's 16-row window
        const int* sps = (const int*)(sm + S_SPS);
        const int spA = sps[16*wm];          // first row of window
        const int spM = sps[16*wm + 7];      // last row of lower half
        const int spB = sps[16*wm + 8];      // first row of upper half
        const int spZ = sps[16*wm + 15];     // last row of window
        const bool uniAll = (spA == spZ);
        const bool uni0   = (spA == spM);
        const bool uni1   = (spB == spZ);
        const int sp0 = sps[16*wm + rb];
        const int sp1 = sps[16*wm + rb + 8];

        // ================= layer 2 =================
        float a2[16][4];
        #pragma unroll
        for (int nt = 0; nt < 16; nt++)
            #pragma unroll
            for (int j = 0; j < 4; j++) a2[nt][j] = 0.f;

        {
            uint32_t ah[2][4], al[2][4];
            {
                uint32_t o = off128((uint32_t)(16*wm + arow), (uint32_t)acol8);
                ldsm4(ah[0], smb + S_HHI + o);
                ldsm4(al[0], smb + S_HLO + o);
            }
            #pragma unroll
            for (int ks = 0; ks < 4; ks++) {
                const int cur = ks & 1;
                if (ks < 3) {
                    uint32_t o = off128((uint32_t)(16*wm + arow),
                                        (uint32_t)(16*(ks + 1) + acol8));
                    ldsm4(ah[cur ^ 1], smb + S_HHI + o);
                    ldsm4(al[cur ^ 1], smb + S_HLO + o);
                }
                #pragma unroll
                for (int nt = 0; nt < 16; nt++) {
                    const uint4 f = __ldg(&g_w2f[((16*wn + nt)*4 + ks)*32 + lane]);
                    mma_bf16(a2[nt], ah[cur], f.x, f.y);
                    mma_bf16(a2[nt], al[cur], f.x, f.y);
                    mma_bf16(a2[nt], ah[cur], f.z, f.w);
                }
            }
        }

        // epilogue 2: bias + relu + warp segmented max (shuffle) -> few atomics
        {
            const float* b2s = (const float*)(sm + S_B2);
            #pragma unroll
            for (int nt = 0; nt < 16; nt++) {
                #pragma unroll
                for (int c01 = 0; c01 < 2; c01++) {
                    const int col = 128*wn + 8*nt + 2*q + c01;
                    const float bias = b2s[col];
                    float v0 = fmaxf(a2[nt][c01]     + bias, 0.f);
                    float v1 = fmaxf(a2[nt][c01 + 2] + bias, 0.f);
                    if (uniAll) {
                        float v = qgroup_max(fmaxf(v0, v1));
                        if (lane < 4)
                            atomicMax(&g_tok[spA * EMBED + col], __float_as_int(v));
                    } else {
                        if (uni0) {
                            float v = qgroup_max(v0);
                            if (lane < 4)
                                atomicMax(&g_tok[spA * EMBED + col], __float_as_int(v));
                        } else {
                            atomicMax(&g_tok[sp0 * EMBED + col], __float_as_int(v0));
                        }
                        if (uni1) {
                            float v = qgroup_max(v1);
                            if (lane < 4)
                                atomicMax(&g_tok[spB * EMBED + col], __float_as_int(v));
                        } else {
                            atomicMax(&g_tok[sp1 * EMBED + col], __float_as_int(v1));
                        }
                    }
                }
            }
        }
    }
}

// ---------------- scatter ----------------
__global__ void k_scatter(const int* __restrict__ idx21,
                          const void* __restrict__ is_masked,
                          float* __restrict__ out)
{
    const int sp = blockIdx.x;
    __shared__ int s_off;
    if (threadIdx.x == 0) {
        const int mode = g_mask_is_i32;
        const int* mi = (const int*)is_masked;
        const unsigned char* mb = (const unsigned char*)is_masked;
        int g = idx21[sp];
        int lo = 0, hi = sp;
        while (lo < hi) { int mid = (lo + hi) >> 1; if (idx21[mid] < g) lo = mid + 1; else hi = mid; }
        bool me = mode ? (mi[sp] != 0) : (mb[sp] != 0);
        int rank = 0;
        for (int j = lo; j < sp; j++) {
            bool fj = mode ? (mi[j] != 0) : (mb[j] != 0);
            rank += (fj == me);
        }
        int b = me ? (NUM_SP2 * PAD_LIMIT * EMBED) : 0;
        s_off = b + (g * PAD_LIMIT + rank) * EMBED;
    }
    __syncthreads();
    float4*       dst = (float4*)(out + s_off);
    const float4* src = (const float4*)((const float*)g_tok + sp * EMBED);
    dst[threadIdx.x] = src[threadIdx.x];
}

// ---------------- launch ----------------
extern "C" void kernel_launch(void* const* d_in, const int* in_sizes, int n_in,
                              void* d_out, int out_size) {
    const float* x     = (const float*)d_in[0];
    const int*   idx10 = (const int*)d_in[1];
    const int*   idx21 = (const int*)d_in[2];
    const void*  msk   = (const void*)d_in[3];
    const float* W1    = (const float*)d_in[4];
    const float* b1    = (const float*)d_in[5];
    const float* W2    = (const float*)d_in[6];
    const float* b2    = (const float*)d_in[7];
    float* out = (float*)d_out;

    cudaFuncSetAttribute(k_main, cudaFuncAttributeMaxDynamicSharedMemorySize, SMEM_TOTAL);

    void* tok_ptr = nullptr;
    cudaGetSymbolAddress(&tok_ptr, g_tok);

    cudaMemsetAsync(out, 0, (size_t)out_size * sizeof(float));
    cudaMemsetAsync(tok_ptr, 0, (size_t)NUM_SP * EMBED * sizeof(int));
    k_prep_w<<<32, 256>>>(W1, W2, (const int*)msk);
    k_main<<<GRID_MAIN, 512, SMEM_TOTAL>>>(x, idx10, b1, b2);
    k_scatter<<<NUM_SP, 64>>>(idx21, msk, out);
}

// round 10
// speedup vs baseline: 1.1525x; 1.1525x over previous
#include <cuda_runtime.h>
#include <cuda_bf16.h>
#include <stdint.h>

#define N_POINTS 262144
#define SP_FEAT  128
#define HIDDEN   64
#define EMBED    256
#define NUM_SP   4096
#define NUM_SP2  256
#define PAD_LIMIT 64
#define TILE_M   128
#define N_TILES  (N_POINTS / TILE_M)   // 2048
#define GRID_MAIN 148

// ---------------- device scratch ----------------
__device__ int g_tok[NUM_SP * EMBED];          // float bits, values >= 0
__device__ int g_mask_is_i32;
// prepacked B fragments (mma.m16n8k16 layout), uint4 = {hi_reg0, hi_reg1, lo_reg0, lo_reg1}
__device__ __align__(16) uint4 g_w1f[8 * 8 * 32];    // [n8][ks][lane] (8 KB)
__device__ __align__(16) uint4 g_w2f[32 * 4 * 32];   // [n8][ks][lane] (64 KB)

// ---------------- helpers ----------------
__device__ __forceinline__ uint32_t smem_u32(const void* p) {
    uint32_t a;
    asm("{ .reg .u64 t; cvta.to.shared.u64 t, %1; cvt.u32.u64 %0, t; }" : "=r"(a) : "l"(p));
    return a;
}
// swizzled byte offset, 256B rows (row 0..15 local, k 0..127)
__device__ __forceinline__ uint32_t off256(uint32_t row, uint32_t k) {
    return row * 256u + (((k >> 3) ^ (row & 7u)) << 4) + (k & 7u) * 2u;
}
// swizzled byte offset, 128B rows (k 0..63)
__device__ __forceinline__ uint32_t off128(uint32_t row, uint32_t k) {
    return row * 128u + ((((k >> 3) ^ (row & 7u)) & 7u) << 4) + (k & 7u) * 2u;
}
__device__ __forceinline__ uint32_t pack_bf2(float a, float b) {
    __nv_bfloat162 t = __floats2bfloat162_rn(a, b);
    return *(uint32_t*)&t;
}
__device__ __forceinline__ void ldsm4(uint32_t r[4], uint32_t addr) {
    asm volatile("ldmatrix.sync.aligned.m8n8.x4.shared.b16 {%0,%1,%2,%3}, [%4];"
                 : "=r"(r[0]), "=r"(r[1]), "=r"(r[2]), "=r"(r[3]) : "r"(addr));
}
__device__ __forceinline__ void mma_bf16(float c[4], const uint32_t a[4],
                                         uint32_t b0, uint32_t b1) {
    asm volatile("mma.sync.aligned.m16n8k16.row.col.f32.bf16.bf16.f32 "
                 "{%0,%1,%2,%3}, {%4,%5,%6,%7}, {%8,%9}, {%0,%1,%2,%3};"
                 : "+f"(c[0]), "+f"(c[1]), "+f"(c[2]), "+f"(c[3])
                 : "r"(a[0]), "r"(a[1]), "r"(a[2]), "r"(a[3]), "r"(b0), "r"(b1));
}
__device__ __forceinline__ void cp_async16(uint32_t dst, const void* src) {
    asm volatile("cp.async.cg.shared.global [%0], [%1], 16;" :: "r"(dst), "l"(src));
}
#define CP_COMMIT() asm volatile("cp.async.commit_group;" ::: "memory")
#define CP_WAIT0()  asm volatile("cp.async.wait_group 0;"  ::: "memory")
#define PBAR(id)    asm volatile("bar.sync %0, 64;" :: "r"(id) : "memory")

// ---------------- smem layout: 8 pair-private arenas ----------------
// per pair (20480 B): stage 8192 | XHI 4096 | XLO 4096 | HHI 2048 | HLO 2048
#define P_STAGE 0
#define P_XHI   8192
#define P_XLO   12288
#define P_HHI   16384
#define P_HLO   18432
#define PAIR_SZ 20480
#define S_B1    (8 * PAIR_SZ)          // 163840, 64 f32
#define S_B2    (S_B1 + 256)           // 256 f32
#define SMEM_TOTAL (S_B2 + 1024)       // 165120

// ---------------- prep kernel ----------------
__global__ void k_prep_w(const float* __restrict__ W1, const float* __restrict__ W2,
                         const int* __restrict__ msk) {
    int i = blockIdx.x * blockDim.x + threadIdx.x;     // 8192 threads
    if (blockIdx.x == 0) {
        __shared__ int bad;
        if (threadIdx.x == 0) bad = 0;
        __syncthreads();
        for (int j = threadIdx.x; j < 1024; j += blockDim.x)
            if ((unsigned)msk[j] > 1u) atomicOr(&bad, 1);
        __syncthreads();
        if (threadIdx.x == 0) g_mask_is_i32 = bad ? 0 : 1;
    }
    if (i < 2048) {                                     // layer1: [n8(8)][ks(8)][lane]
        int lane = i & 31, ks = (i >> 5) & 7, n8 = i >> 8;
        int n  = 8 * n8 + (lane >> 2);
        int k0 = 16 * ks + 2 * (lane & 3);
        float v00 = W1[k0 * HIDDEN + n],       v01 = W1[(k0 + 1) * HIDDEN + n];
        float v10 = W1[(k0 + 8) * HIDDEN + n], v11 = W1[(k0 + 9) * HIDDEN + n];
        __nv_bfloat16 h00 = __float2bfloat16_rn(v00), h01 = __float2bfloat16_rn(v01);
        __nv_bfloat16 h10 = __float2bfloat16_rn(v10), h11 = __float2bfloat16_rn(v11);
        uint4 f;
        f.x = pack_bf2(v00, v01);
        f.y = pack_bf2(v10, v11);
        f.z = pack_bf2(v00 - __bfloat162float(h00), v01 - __bfloat162float(h01));
        f.w = pack_bf2(v10 - __bfloat162float(h10), v11 - __bfloat162float(h11));
        g_w1f[i] = f;
    } else if (i < 2048 + 4096) {                       // layer2: [n8(32)][ks(4)][lane]
        int j = i - 2048;
        int lane = j & 31, ks = (j >> 5) & 3, n8 = j >> 7;
        int n  = 8 * n8 + (lane >> 2);
        int k0 = 16 * ks + 2 * (lane & 3);
        float v00 = W2[k0 * EMBED + n],       v01 = W2[(k0 + 1) * EMBED + n];
        float v10 = W2[(k0 + 8) * EMBED + n], v11 = W2[(k0 + 9) * EMBED + n];
        __nv_bfloat16 h00 = __float2bfloat16_rn(v00), h01 = __float2bfloat16_rn(v01);
        __nv_bfloat16 h10 = __float2bfloat16_rn(v10), h11 = __float2bfloat16_rn(v11);
        uint4 f;
        f.x = pack_bf2(v00, v01);
        f.y = pack_bf2(v10, v11);
        f.z = pack_bf2(v00 - __bfloat162float(h00), v01 - __bfloat162float(h01));
        f.w = pack_bf2(v10 - __bfloat162float(h10), v11 - __bfloat162float(h11));
        g_w2f[j] = f;
    }
}

// ---------------- persistent main kernel: 8 independent warp-pair pipelines ----------------
// warp = (wm = wid>>1, wn = wid&1): rows 16wm..+15; L1 cols 32wn..+31; L2 cols 128wn..+127
__global__ __launch_bounds__(512, 1)
void k_main(const float* __restrict__ x, const int* __restrict__ idx10,
            const float* __restrict__ b1, const float* __restrict__ b2)
{
    extern __shared__ char sm[];
    const uint32_t smb = smem_u32(sm);
    const int tid  = threadIdx.x;
    const int wid  = tid >> 5;
    const int lane = tid & 31;
    const int wm   = wid >> 1;        // pair id 0..7, rows 16wm..+15
    const int wn   = wid & 1;
    const int tip  = tid & 63;        // thread-in-pair
    const int q    = lane & 3;
    const int rb   = lane >> 2;
    const int arow  = lane & 15;
    const int acol8 = (lane >> 4) * 8;
    const int barid = wm + 1;

    const uint32_t pb = smb + (uint32_t)wm * PAIR_SZ;   // pair arena base

    if (tid < 64)  ((float*)(sm + S_B1))[tid] = b1[tid];
    if (tid < 256) ((float*)(sm + S_B2))[tid] = b2[tid];
    __syncthreads();   // biases visible to all pairs once, before the loop

    // prologue: prefetch own 16 rows of tile t0
    int t = blockIdx.x;
    {
        const float* src = x + ((size_t)t * TILE_M + 16 * wm) * SP_FEAT;
        #pragma unroll
        for (int j = 0; j < 8; j++) {
            int i = tip + j * 64;                 // 512 uint4 = 16 rows x 32
            cp_async16(pb + P_STAGE + i * 16, src + i * 4);
        }
    }
    CP_COMMIT();

    for (; t < N_TILES; t += GRID_MAIN) {
        CP_WAIT0();
        PBAR(barid);                              // stage(t) ready for whole pair

        // convert own stage -> XHI/XLO (local rows 0..15)
        #pragma unroll
        for (int j = 0; j < 8; j++) {
            int i = tip + j * 64;
            int p = i >> 5, c4 = i & 31;
            float4 v = ((const float4*)(sm + (wm * PAIR_SZ + P_STAGE)))[i];
            __nv_bfloat16 h0 = __float2bfloat16_rn(v.x), h1 = __float2bfloat16_rn(v.y);
            __nv_bfloat16 h2 = __float2bfloat16_rn(v.z), h3 = __float2bfloat16_rn(v.w);
            uint2 hi = make_uint2(pack_bf2(v.x, v.y), pack_bf2(v.z, v.w));
            uint2 lo = make_uint2(pack_bf2(v.x - __bfloat162float(h0), v.y - __bfloat162float(h1)),
                                  pack_bf2(v.z - __bfloat162float(h2), v.w - __bfloat162float(h3)));
            uint32_t off = off256((uint32_t)p, (uint32_t)(c4 * 4));
            *(uint2*)(sm + wm * PAIR_SZ + P_XHI + off) = hi;
            *(uint2*)(sm + wm * PAIR_SZ + P_XLO + off) = lo;
        }
        PBAR(barid);                              // XHI/XLO ready; stage reads done

        // prefetch next tile's own rows (stage free now)
        {
            int tn = t + GRID_MAIN;
            if (tn < N_TILES) {
                const float* src = x + ((size_t)tn * TILE_M + 16 * wm) * SP_FEAT;
                #pragma unroll
                for (int j = 0; j < 8; j++) {
                    int i = tip + j * 64;
                    cp_async16(pb + P_STAGE + i * 16, src + i * 4);
                }
            }
            CP_COMMIT();
        }

        // ================= layer 1: local 16 rows, cols 32wn..+31 =================
        float acc[4][4];
        #pragma unroll
        for (int nth = 0; nth < 4; nth++)
            #pragma unroll
            for (int j = 0; j < 4; j++) acc[nth][j] = 0.f;

        {
            uint32_t ah[2][4], al[2][4];
            {
                uint32_t o = off256((uint32_t)arow, (uint32_t)acol8);
                ldsm4(ah[0], pb + P_XHI + o);
                ldsm4(al[0], pb + P_XLO + o);
            }
            #pragma unroll
            for (int ks = 0; ks < 8; ks++) {
                const int cur = ks & 1;
                if (ks < 7) {
                    uint32_t o = off256((uint32_t)arow, (uint32_t)(16 * (ks + 1) + acol8));
                    ldsm4(ah[cur ^ 1], pb + P_XHI + o);
                    ldsm4(al[cur ^ 1], pb + P_XLO + o);
                }
                #pragma unroll
                for (int nth = 0; nth < 4; nth++) {
                    const uint4 f = __ldg(&g_w1f[((4*wn + nth)*8 + ks)*32 + lane]);
                    mma_bf16(acc[nth], ah[cur], f.x, f.y);
                    mma_bf16(acc[nth], al[cur], f.x, f.y);
                    mma_bf16(acc[nth], ah[cur], f.z, f.w);
                }
            }
        }

        // epilogue 1: bias + relu -> bf16 hi/lo into pair H (local rows)
        {
            const float* b1s = (const float*)(sm + S_B1);
            #pragma unroll
            for (int nth = 0; nth < 4; nth++) {
                const int col = 32*wn + 8*nth + 2*q;
                const float bia0 = b1s[col], bia1 = b1s[col + 1];
                int r1 = rb, r2 = rb + 8;
                float v00 = fmaxf(acc[nth][0] + bia0, 0.f);
                float v01 = fmaxf(acc[nth][1] + bia1, 0.f);
                float v10 = fmaxf(acc[nth][2] + bia0, 0.f);
                float v11 = fmaxf(acc[nth][3] + bia1, 0.f);
                __nv_bfloat16 h00 = __float2bfloat16_rn(v00), h01 = __float2bfloat16_rn(v01);
                __nv_bfloat16 h10 = __float2bfloat16_rn(v10), h11 = __float2bfloat16_rn(v11);
                uint32_t o1 = off128((uint32_t)r1, (uint32_t)col);
                uint32_t o2 = off128((uint32_t)r2, (uint32_t)col);
                *(uint32_t*)(sm + wm * PAIR_SZ + P_HHI + o1) = pack_bf2(v00, v01);
                *(uint32_t*)(sm + wm * PAIR_SZ + P_HHI + o2) = pack_bf2(v10, v11);
                *(uint32_t*)(sm + wm * PAIR_SZ + P_HLO + o1) = pack_bf2(v00 - __bfloat162float(h00),
                                                                        v01 - __bfloat162float(h01));
                *(uint32_t*)(sm + wm * PAIR_SZ + P_HLO + o2) = pack_bf2(v10 - __bfloat162float(h10),
                                                                        v11 - __bfloat162float(h11));
            }
        }
        PBAR(barid);                              // H ready (needs both warps of pair)

        // sp ids for this thread's fragment rows (direct LDG, L2-hot, broadcast)
        const int sp0 = idx10[t * TILE_M + 16*wm + rb];
        const int sp1 = idx10[t * TILE_M + 16*wm + rb + 8];

        // ================= layer 2: local 16 rows, cols 128wn..+127 =================
        float a2[16][4];
        #pragma unroll
        for (int nt = 0; nt < 16; nt++)
            #pragma unroll
            for (int j = 0; j < 4; j++) a2[nt][j] = 0.f;

        {
            uint32_t ah[2][4], al[2][4];
            {
                uint32_t o = off128((uint32_t)arow, (uint32_t)acol8);
                ldsm4(ah[0], pb + P_HHI + o);
                ldsm4(al[0], pb + P_HLO + o);
            }
            #pragma unroll
            for (int ks = 0; ks < 4; ks++) {
                const int cur = ks & 1;
                if (ks < 3) {
                    uint32_t o = off128((uint32_t)arow, (uint32_t)(16 * (ks + 1) + acol8));
                    ldsm4(ah[cur ^ 1], pb + P_HHI + o);
                    ldsm4(al[cur ^ 1], pb + P_HLO + o);
                }
                #pragma unroll
                for (int nt = 0; nt < 16; nt++) {
                    const uint4 f = __ldg(&g_w2f[((16*wn + nt)*4 + ks)*32 + lane]);
                    mma_bf16(a2[nt], ah[cur], f.x, f.y);
                    mma_bf16(a2[nt], al[cur], f.x, f.y);
                    mma_bf16(a2[nt], ah[cur], f.z, f.w);
                }
            }
        }

        // epilogue 2: bias + relu + 2-row segmented max -> atomicMax (R8 form)
        {
            const float* b2s = (const float*)(sm + S_B2);
            #pragma unroll
            for (int nt = 0; nt < 16; nt++) {
                int colb = 128*wn + 8*nt + 2*q;
                #pragma unroll
                for (int c01 = 0; c01 < 2; c01++) {
                    int col = colb + c01;
                    float bias = b2s[col];
                    float v0 = fmaxf(a2[nt][c01]     + bias, 0.f);
                    float v1 = fmaxf(a2[nt][c01 + 2] + bias, 0.f);
                    if (sp0 == sp1) {
                        atomicMax(&g_tok[sp0 * EMBED + col],
                                  __float_as_int(fmaxf(v0, v1)));
                    } else {
                        atomicMax(&g_tok[sp0 * EMBED + col], __float_as_int(v0));
                        atomicMax(&g_tok[sp1 * EMBED + col], __float_as_int(v1));
                    }
                }
            }
        }
        // loop-top CP_WAIT0 + PBAR orders next-iter writes after this iter's reads
    }
}

// ---------------- scatter ----------------
__global__ void k_scatter(const int* __restrict__ idx21,
                          const void* __restrict__ is_masked,
                          float* __restrict__ out)
{
    const int sp = blockIdx.x;
    __shared__ int s_off;
    if (threadIdx.x == 0) {
        const int mode = g_mask_is_i32;
        const int* mi = (const int*)is_masked;
        const unsigned char* mb = (const unsigned char*)is_masked;
        int g = idx21[sp];
        int lo = 0, hi = sp;
        while (lo < hi) { int mid = (lo + hi) >> 1; if (idx21[mid] < g) lo = mid + 1; else hi = mid; }
        bool me = mode ? (mi[sp] != 0) : (mb[sp] != 0);
        int rank = 0;
        for (int j = lo; j < sp; j++) {
            bool fj = mode ? (mi[j] != 0) : (mb[j] != 0);
            rank += (fj == me);
        }
        int b = me ? (NUM_SP2 * PAD_LIMIT * EMBED) : 0;
        s_off = b + (g * PAD_LIMIT + rank) * EMBED;
    }
    __syncthreads();
    float4*       dst = (float4*)(out + s_off);
    const float4* src = (const float4*)((const float*)g_tok + sp * EMBED);
    dst[threadIdx.x] = src[threadIdx.x];
}

// ---------------- launch ----------------
extern "C" void kernel_launch(void* const* d_in, const int* in_sizes, int n_in,
                              void* d_out, int out_size) {
    const float* x     = (const float*)d_in[0];
    const int*   idx10 = (const int*)d_in[1];
    const int*   idx21 = (const int*)d_in[2];
    const void*  msk   = (const void*)d_in[3];
    const float* W1    = (const float*)d_in[4];
    const float* b1    = (const float*)d_in[5];
    const float* W2    = (const float*)d_in[6];
    const float* b2    = (const float*)d_in[7];
    float* out = (float*)d_out;

    cudaFuncSetAttribute(k_main, cudaFuncAttributeMaxDynamicSharedMemorySize, SMEM_TOTAL);

    void* tok_ptr = nullptr;
    cudaGetSymbolAddress(&tok_ptr, g_tok);

    cudaMemsetAsync(out, 0, (size_t)out_size * sizeof(float));
    cudaMemsetAsync(tok_ptr, 0, (size_t)NUM_SP * EMBED * sizeof(int));
    k_prep_w<<<32, 256>>>(W1, W2, (const int*)msk);
    k_main<<<GRID_MAIN, 512, SMEM_TOTAL>>>(x, idx10, b1, b2);
    k_scatter<<<NUM_SP, 64>>>(idx21, msk, out);
}

// round 11
// speedup vs baseline: 1.2470x; 1.0820x over previous
#include <cuda_runtime.h>
#include <cuda_bf16.h>
#include <stdint.h>

#define N_POINTS 262144
#define SP_FEAT  128
#define HIDDEN   64
#define EMBED    256
#define NUM_SP   4096
#define NUM_SP2  256
#define PAD_LIMIT 64
#define TILE_M   128
#define N_TILES  (N_POINTS / TILE_M)   // 2048
#define GRID_MAIN 148

// ---------------- device scratch ----------------
__device__ int g_tok[NUM_SP * EMBED];          // float bits, values >= 0
__device__ int g_mask_is_i32;
// prepacked B fragments (mma.m16n8k16 layout), uint4 = {hi_reg0, hi_reg1, lo_reg0, lo_reg1}
__device__ __align__(16) uint4 g_w1f[8 * 8 * 32];    // [n8][ks][lane] (8 KB)
__device__ __align__(16) uint4 g_w2f[32 * 4 * 32];   // [n8][ks][lane] (64 KB)

// ---------------- helpers ----------------
__device__ __forceinline__ uint32_t smem_u32(const void* p) {
    uint32_t a;
    asm("{ .reg .u64 t; cvta.to.shared.u64 t, %1; cvt.u32.u64 %0, t; }" : "=r"(a) : "l"(p));
    return a;
}
// swizzled byte offset, 256B rows (row local, k 0..127)
__device__ __forceinline__ uint32_t off256(uint32_t row, uint32_t k) {
    return row * 256u + (((k >> 3) ^ (row & 7u)) << 4) + (k & 7u) * 2u;
}
// swizzled byte offset, 128B rows (k 0..63)
__device__ __forceinline__ uint32_t off128(uint32_t row, uint32_t k) {
    return row * 128u + ((((k >> 3) ^ (row & 7u)) & 7u) << 4) + (k & 7u) * 2u;
}
__device__ __forceinline__ uint32_t pack_bf2(float a, float b) {
    __nv_bfloat162 t = __floats2bfloat162_rn(a, b);
    return *(uint32_t*)&t;
}
__device__ __forceinline__ void ldsm4(uint32_t r[4], uint32_t addr) {
    asm volatile("ldmatrix.sync.aligned.m8n8.x4.shared.b16 {%0,%1,%2,%3}, [%4];"
                 : "=r"(r[0]), "=r"(r[1]), "=r"(r[2]), "=r"(r[3]) : "r"(addr));
}
__device__ __forceinline__ void mma_bf16(float c[4], const uint32_t a[4],
                                         uint32_t b0, uint32_t b1) {
    asm volatile("mma.sync.aligned.m16n8k16.row.col.f32.bf16.bf16.f32 "
                 "{%0,%1,%2,%3}, {%4,%5,%6,%7}, {%8,%9}, {%0,%1,%2,%3};"
                 : "+f"(c[0]), "+f"(c[1]), "+f"(c[2]), "+f"(c[3])
                 : "r"(a[0]), "r"(a[1]), "r"(a[2]), "r"(a[3]), "r"(b0), "r"(b1));
}
__device__ __forceinline__ void cp_async16(uint32_t dst, const void* src) {
    asm volatile("cp.async.cg.shared.global [%0], [%1], 16;" :: "r"(dst), "l"(src));
}
#define CP_COMMIT() asm volatile("cp.async.commit_group;" ::: "memory")
#define CP_WAIT0()  asm volatile("cp.async.wait_group 0;"  ::: "memory")
#define QBAR(id)    asm volatile("bar.sync %0, 128;" :: "r"(id) : "memory")

// ---------------- smem layout: 4 quad-private arenas ----------------
// per quad (40960 B): stage 16384 | XHI 8192 | XLO 8192 | HHI 4096 | HLO 4096
#define Q_STAGE 0
#define Q_XHI   16384
#define Q_XLO   24576
#define Q_HHI   32768
#define Q_HLO   36864
#define QUAD_SZ 40960
#define S_B1    (4 * QUAD_SZ)          // 163840, 64 f32
#define S_B2    (S_B1 + 256)           // 256 f32
#define SMEM_TOTAL (S_B2 + 1024)       // 165120

// ---------------- prep kernel ----------------
__global__ void k_prep_w(const float* __restrict__ W1, const float* __restrict__ W2,
                         const int* __restrict__ msk) {
    int i = blockIdx.x * blockDim.x + threadIdx.x;     // 8192 threads
    if (blockIdx.x == 0) {
        __shared__ int bad;
        if (threadIdx.x == 0) bad = 0;
        __syncthreads();
        for (int j = threadIdx.x; j < 1024; j += blockDim.x)
            if ((unsigned)msk[j] > 1u) atomicOr(&bad, 1);
        __syncthreads();
        if (threadIdx.x == 0) g_mask_is_i32 = bad ? 0 : 1;
    }
    if (i < 2048) {                                     // layer1: [n8(8)][ks(8)][lane]
        int lane = i & 31, ks = (i >> 5) & 7, n8 = i >> 8;
        int n  = 8 * n8 + (lane >> 2);
        int k0 = 16 * ks + 2 * (lane & 3);
        float v00 = W1[k0 * HIDDEN + n],       v01 = W1[(k0 + 1) * HIDDEN + n];
        float v10 = W1[(k0 + 8) * HIDDEN + n], v11 = W1[(k0 + 9) * HIDDEN + n];
        __nv_bfloat16 h00 = __float2bfloat16_rn(v00), h01 = __float2bfloat16_rn(v01);
        __nv_bfloat16 h10 = __float2bfloat16_rn(v10), h11 = __float2bfloat16_rn(v11);
        uint4 f;
        f.x = pack_bf2(v00, v01);
        f.y = pack_bf2(v10, v11);
        f.z = pack_bf2(v00 - __bfloat162float(h00), v01 - __bfloat162float(h01));
        f.w = pack_bf2(v10 - __bfloat162float(h10), v11 - __bfloat162float(h11));
        g_w1f[i] = f;
    } else if (i < 2048 + 4096) {                       // layer2: [n8(32)][ks(4)][lane]
        int j = i - 2048;
        int lane = j & 31, ks = (j >> 5) & 3, n8 = j >> 7;
        int n  = 8 * n8 + (lane >> 2);
        int k0 = 16 * ks + 2 * (lane & 3);
        float v00 = W2[k0 * EMBED + n],       v01 = W2[(k0 + 1) * EMBED + n];
        float v10 = W2[(k0 + 8) * EMBED + n], v11 = W2[(k0 + 9) * EMBED + n];
        __nv_bfloat16 h00 = __float2bfloat16_rn(v00), h01 = __float2bfloat16_rn(v01);
        __nv_bfloat16 h10 = __float2bfloat16_rn(v10), h11 = __float2bfloat16_rn(v11);
        uint4 f;
        f.x = pack_bf2(v00, v01);
        f.y = pack_bf2(v10, v11);
        f.z = pack_bf2(v00 - __bfloat162float(h00), v01 - __bfloat162float(h01));
        f.w = pack_bf2(v10 - __bfloat162float(h10), v11 - __bfloat162float(h11));
        g_w2f[j] = f;
    }
}

// ---------------- persistent main kernel: 4 independent 4-warp quad pipelines ----------------
// quad qid = wid>>2 owns rows 32qid..+31; warp wq = wid&3:
//   layer1 cols 16wq..+15, layer2 cols 64wq..+63, both over the quad's 32 rows (mt=0,1)
__global__ __launch_bounds__(512, 1)
void k_main(const float* __restrict__ x, const int* __restrict__ idx10,
            const float* __restrict__ b1, const float* __restrict__ b2)
{
    extern __shared__ char sm[];
    const uint32_t smb = smem_u32(sm);
    const int tid  = threadIdx.x;
    const int wid  = tid >> 5;
    const int lane = tid & 31;
    const int qid  = wid >> 2;        // quad 0..3, rows 32qid..+31
    const int wq   = wid & 3;
    const int tiq  = tid & 127;       // thread-in-quad
    const int q    = lane & 3;
    const int rb   = lane >> 2;
    const int arow  = lane & 15;
    const int acol8 = (lane >> 4) * 8;
    const int barid = qid + 1;

    const uint32_t qb = smb + (uint32_t)qid * QUAD_SZ;

    if (tid < 64)  ((float*)(sm + S_B1))[tid] = b1[tid];
    if (tid < 256) ((float*)(sm + S_B2))[tid] = b2[tid];
    __syncthreads();   // biases visible once

    // prologue: prefetch own 32 rows of tile t0 (1024 uint4 per quad)
    int t = blockIdx.x;
    {
        const float* src = x + ((size_t)t * TILE_M + 32 * qid) * SP_FEAT;
        #pragma unroll
        for (int j = 0; j < 8; j++) {
            int i = tiq + j * 128;
            cp_async16(qb + Q_STAGE + i * 16, src + i * 4);
        }
    }
    CP_COMMIT();

    for (; t < N_TILES; t += GRID_MAIN) {
        CP_WAIT0();
        QBAR(barid);                              // stage(t) ready for whole quad

        // convert own stage -> XHI/XLO (local rows 0..31)
        #pragma unroll
        for (int j = 0; j < 8; j++) {
            int i = tiq + j * 128;
            int p = i >> 5, c4 = i & 31;
            float4 v = ((const float4*)(sm + (qid * QUAD_SZ + Q_STAGE)))[i];
            __nv_bfloat16 h0 = __float2bfloat16_rn(v.x), h1 = __float2bfloat16_rn(v.y);
            __nv_bfloat16 h2 = __float2bfloat16_rn(v.z), h3 = __float2bfloat16_rn(v.w);
            uint2 hi = make_uint2(pack_bf2(v.x, v.y), pack_bf2(v.z, v.w));
            uint2 lo = make_uint2(pack_bf2(v.x - __bfloat162float(h0), v.y - __bfloat162float(h1)),
                                  pack_bf2(v.z - __bfloat162float(h2), v.w - __bfloat162float(h3)));
            uint32_t off = off256((uint32_t)p, (uint32_t)(c4 * 4));
            *(uint2*)(sm + qid * QUAD_SZ + Q_XHI + off) = hi;
            *(uint2*)(sm + qid * QUAD_SZ + Q_XLO + off) = lo;
        }
        QBAR(barid);                              // XHI/XLO ready; stage reads done

        // prefetch next tile's own rows
        {
            int tn = t + GRID_MAIN;
            if (tn < N_TILES) {
                const float* src = x + ((size_t)tn * TILE_M + 32 * qid) * SP_FEAT;
                #pragma unroll
                for (int j = 0; j < 8; j++) {
                    int i = tiq + j * 128;
                    cp_async16(qb + Q_STAGE + i * 16, src + i * 4);
                }
            }
            CP_COMMIT();
        }

        // ================= layer 1: local 32 rows (mt 0,1), cols 16wq..+15 =================
        float acc[2][2][4];   // [mt][nth][4]
        #pragma unroll
        for (int mt = 0; mt < 2; mt++)
            #pragma unroll
            for (int nth = 0; nth < 2; nth++)
                #pragma unroll
                for (int j = 0; j < 4; j++) acc[mt][nth][j] = 0.f;

        {
            uint32_t ah[2][2][4], al[2][2][4];   // [buf][mt]
            #pragma unroll
            for (int mt = 0; mt < 2; mt++) {
                uint32_t o = off256((uint32_t)(16*mt + arow), (uint32_t)acol8);
                ldsm4(ah[0][mt], qb + Q_XHI + o);
                ldsm4(al[0][mt], qb + Q_XLO + o);
            }
            #pragma unroll
            for (int ks = 0; ks < 8; ks++) {
                const int cur = ks & 1;
                if (ks < 7) {
                    #pragma unroll
                    for (int mt = 0; mt < 2; mt++) {
                        uint32_t o = off256((uint32_t)(16*mt + arow),
                                            (uint32_t)(16*(ks + 1) + acol8));
                        ldsm4(ah[cur ^ 1][mt], qb + Q_XHI + o);
                        ldsm4(al[cur ^ 1][mt], qb + Q_XLO + o);
                    }
                }
                #pragma unroll
                for (int nth = 0; nth < 2; nth++) {
                    const uint4 f = __ldg(&g_w1f[((2*wq + nth)*8 + ks)*32 + lane]);
                    #pragma unroll
                    for (int mt = 0; mt < 2; mt++) {
                        mma_bf16(acc[mt][nth], ah[cur][mt], f.x, f.y);
                        mma_bf16(acc[mt][nth], al[cur][mt], f.x, f.y);
                        mma_bf16(acc[mt][nth], ah[cur][mt], f.z, f.w);
                    }
                }
            }
        }

        // epilogue 1: bias + relu -> bf16 hi/lo into quad H (local rows)
        {
            const float* b1s = (const float*)(sm + S_B1);
            #pragma unroll
            for (int nth = 0; nth < 2; nth++) {
                const int col = 16*wq + 8*nth + 2*q;
                const float bia0 = b1s[col], bia1 = b1s[col + 1];
                #pragma unroll
                for (int mt = 0; mt < 2; mt++) {
                    int r1 = 16*mt + rb, r2 = r1 + 8;
                    float v00 = fmaxf(acc[mt][nth][0] + bia0, 0.f);
                    float v01 = fmaxf(acc[mt][nth][1] + bia1, 0.f);
                    float v10 = fmaxf(acc[mt][nth][2] + bia0, 0.f);
                    float v11 = fmaxf(acc[mt][nth][3] + bia1, 0.f);
                    __nv_bfloat16 h00 = __float2bfloat16_rn(v00), h01 = __float2bfloat16_rn(v01);
                    __nv_bfloat16 h10 = __float2bfloat16_rn(v10), h11 = __float2bfloat16_rn(v11);
                    uint32_t o1 = off128((uint32_t)r1, (uint32_t)col);
                    uint32_t o2 = off128((uint32_t)r2, (uint32_t)col);
                    *(uint32_t*)(sm + qid * QUAD_SZ + Q_HHI + o1) = pack_bf2(v00, v01);
                    *(uint32_t*)(sm + qid * QUAD_SZ + Q_HHI + o2) = pack_bf2(v10, v11);
                    *(uint32_t*)(sm + qid * QUAD_SZ + Q_HLO + o1) =
                        pack_bf2(v00 - __bfloat162float(h00), v01 - __bfloat162float(h01));
                    *(uint32_t*)(sm + qid * QUAD_SZ + Q_HLO + o2) =
                        pack_bf2(v10 - __bfloat162float(h10), v11 - __bfloat162float(h11));
                }
            }
        }
        QBAR(barid);                              // H ready (all 4 warps of quad)

        // sp ids for this thread's fragment rows (direct LDG, L2-hot broadcast)
        int sp0[2], sp1[2];
        #pragma unroll
        for (int mt = 0; mt < 2; mt++) {
            sp0[mt] = idx10[t * TILE_M + 32*qid + 16*mt + rb];
            sp1[mt] = idx10[t * TILE_M + 32*qid + 16*mt + rb + 8];
        }

        // ================= layer 2: local 32 rows, cols 64wq..+63 =================
        float a2[8][2][4];   // [nt][mt][4] = 64 regs
        #pragma unroll
        for (int nt = 0; nt < 8; nt++)
            #pragma unroll
            for (int mt = 0; mt < 2; mt++)
                #pragma unroll
                for (int j = 0; j < 4; j++) a2[nt][mt][j] = 0.f;

        {
            uint32_t ah[2][2][4], al[2][2][4];   // [buf][mt]
            #pragma unroll
            for (int mt = 0; mt < 2; mt++) {
                uint32_t o = off128((uint32_t)(16*mt + arow), (uint32_t)acol8);
                ldsm4(ah[0][mt], qb + Q_HHI + o);
                ldsm4(al[0][mt], qb + Q_HLO + o);
            }
            #pragma unroll
            for (int ks = 0; ks < 4; ks++) {
                const int cur = ks & 1;
                if (ks < 3) {
                    #pragma unroll
                    for (int mt = 0; mt < 2; mt++) {
                        uint32_t o = off128((uint32_t)(16*mt + arow),
                                            (uint32_t)(16*(ks + 1) + acol8));
                        ldsm4(ah[cur ^ 1][mt], qb + Q_HHI + o);
                        ldsm4(al[cur ^ 1][mt], qb + Q_HLO + o);
                    }
                }
                #pragma unroll
                for (int nt = 0; nt < 8; nt++) {
                    const uint4 f = __ldg(&g_w2f[((8*wq + nt)*4 + ks)*32 + lane]);
                    #pragma unroll
                    for (int mt = 0; mt < 2; mt++) {
                        mma_bf16(a2[nt][mt], ah[cur][mt], f.x, f.y);
                        mma_bf16(a2[nt][mt], al[cur][mt], f.x, f.y);
                        mma_bf16(a2[nt][mt], ah[cur][mt], f.z, f.w);
                    }
                }
            }
        }

        // epilogue 2: bias + relu + 2-row segmented max -> atomicMax
        {
            const float* b2s = (const float*)(sm + S_B2);
            #pragma unroll
            for (int nt = 0; nt < 8; nt++) {
                int colb = 64*wq + 8*nt + 2*q;
                #pragma unroll
                for (int c01 = 0; c01 < 2; c01++) {
                    int col = colb + c01;
                    float bias = b2s[col];
                    #pragma unroll
                    for (int mt = 0; mt < 2; mt++) {
                        float v0 = fmaxf(a2[nt][mt][c01]     + bias, 0.f);
                        float v1 = fmaxf(a2[nt][mt][c01 + 2] + bias, 0.f);
                        if (sp0[mt] == sp1[mt]) {
                            atomicMax(&g_tok[sp0[mt] * EMBED + col],
                                      __float_as_int(fmaxf(v0, v1)));
                        } else {
                            atomicMax(&g_tok[sp0[mt] * EMBED + col], __float_as_int(v0));
                            atomicMax(&g_tok[sp1[mt] * EMBED + col], __float_as_int(v1));
                        }
                    }
                }
            }
        }
        // loop-top CP_WAIT0 + QBAR orders next-iter writes after this iter's reads
    }
}

// ---------------- scatter ----------------
__global__ void k_scatter(const int* __restrict__ idx21,
                          const void* __restrict__ is_masked,
                          float* __restrict__ out)
{
    const int sp = blockIdx.x;
    __shared__ int s_off;
    if (threadIdx.x == 0) {
        const int mode = g_mask_is_i32;
        const int* mi = (const int*)is_masked;
        const unsigned char* mb = (const unsigned char*)is_masked;
        int g = idx21[sp];
        int lo = 0, hi = sp;
        while (lo < hi) { int mid = (lo + hi) >> 1; if (idx21[mid] < g) lo = mid + 1; else hi = mid; }
        bool me = mode ? (mi[sp] != 0) : (mb[sp] != 0);
        int rank = 0;
        for (int j = lo; j < sp; j++) {
            bool fj = mode ? (mi[j] != 0) : (mb[j] != 0);
            rank += (fj == me);
        }
        int b = me ? (NUM_SP2 * PAD_LIMIT * EMBED) : 0;
        s_off = b + (g * PAD_LIMIT + rank) * EMBED;
    }
    __syncthreads();
    float4*       dst = (float4*)(out + s_off);
    const float4* src = (const float4*)((const float*)g_tok + sp * EMBED);
    dst[threadIdx.x] = src[threadIdx.x];
}

// ---------------- launch ----------------
extern "C" void kernel_launch(void* const* d_in, const int* in_sizes, int n_in,
                              void* d_out, int out_size) {
    const float* x     = (const float*)d_in[0];
    const int*   idx10 = (const int*)d_in[1];
    const int*   idx21 = (const int*)d_in[2];
    const void*  msk   = (const void*)d_in[3];
    const float* W1    = (const float*)d_in[4];
    const float* b1    = (const float*)d_in[5];
    const float* W2    = (const float*)d_in[6];
    const float* b2    = (const float*)d_in[7];
    float* out = (float*)d_out;

    cudaFuncSetAttribute(k_main, cudaFuncAttributeMaxDynamicSharedMemorySize, SMEM_TOTAL);

    void* tok_ptr = nullptr;
    cudaGetSymbolAddress(&tok_ptr, g_tok);

    cudaMemsetAsync(out, 0, (size_t)out_size * sizeof(float));
    cudaMemsetAsync(tok_ptr, 0, (size_t)NUM_SP * EMBED * sizeof(int));
    k_prep_w<<<32, 256>>>(W1, W2, (const int*)msk);
    k_main<<<GRID_MAIN, 512, SMEM_TOTAL>>>(x, idx10, b1, b2);
    k_scatter<<<NUM_SP, 64>>>(idx21, msk, out);
}

// round 12
// speedup vs baseline: 1.4254x; 1.1431x over previous
#include <cuda_runtime.h>
#include <cuda_bf16.h>
#include <stdint.h>

#define N_POINTS 262144
#define SP_FEAT  128
#define HIDDEN   64
#define EMBED    256
#define NUM_SP   4096
#define NUM_SP2  256
#define PAD_LIMIT 64
#define SUB_M    32
#define NSUB     (N_POINTS / SUB_M)    // 8192
#define GRID_MAIN 148
#define NQUAD    6

// ---------------- device scratch ----------------
__device__ int g_tok[NUM_SP * EMBED];          // float bits, values >= 0
__device__ int g_mask_is_i32;
__device__ int g_work;                         // work queue head (reset by k_prep_w)
// prepacked B fragments (mma.m16n8k16), uint4 = {hi_reg0, hi_reg1, lo_reg0, lo_reg1}
__device__ __align__(16) uint4 g_w1f[8 * 8 * 32];    // [n8][ks][lane] (8 KB)
__device__ __align__(16) uint4 g_w2f[32 * 4 * 32];   // [n8][ks][lane] (64 KB)

// ---------------- helpers ----------------
__device__ __forceinline__ uint32_t smem_u32(const void* p) {
    uint32_t a;
    asm("{ .reg .u64 t; cvta.to.shared.u64 t, %1; cvt.u32.u64 %0, t; }" : "=r"(a) : "l"(p));
    return a;
}
__device__ __forceinline__ uint32_t off256(uint32_t row, uint32_t k) {
    return row * 256u + (((k >> 3) ^ (row & 7u)) << 4) + (k & 7u) * 2u;
}
__device__ __forceinline__ uint32_t off128(uint32_t row, uint32_t k) {
    return row * 128u + ((((k >> 3) ^ (row & 7u)) & 7u) << 4) + (k & 7u) * 2u;
}
__device__ __forceinline__ uint32_t pack_bf2(float a, float b) {
    __nv_bfloat162 t = __floats2bfloat162_rn(a, b);
    return *(uint32_t*)&t;
}
__device__ __forceinline__ void ldsm4(uint32_t r[4], uint32_t addr) {
    asm volatile("ldmatrix.sync.aligned.m8n8.x4.shared.b16 {%0,%1,%2,%3}, [%4];"
                 : "=r"(r[0]), "=r"(r[1]), "=r"(r[2]), "=r"(r[3]) : "r"(addr));
}
__device__ __forceinline__ void mma_bf16(float c[4], const uint32_t a[4],
                                         uint32_t b0, uint32_t b1) {
    asm volatile("mma.sync.aligned.m16n8k16.row.col.f32.bf16.bf16.f32 "
                 "{%0,%1,%2,%3}, {%4,%5,%6,%7}, {%8,%9}, {%0,%1,%2,%3};"
                 : "+f"(c[0]), "+f"(c[1]), "+f"(c[2]), "+f"(c[3])
                 : "r"(a[0]), "r"(a[1]), "r"(a[2]), "r"(a[3]), "r"(b0), "r"(b1));
}
#define QBAR(id) asm volatile("bar.sync %0, 128;" :: "r"(id) : "memory")

// ---------------- smem layout: 6 quad-private arenas ----------------
// per quad (24576 B): XHI 8192 | XLO 8192 | HHI 4096 | HLO 4096
#define Q_XHI   0
#define Q_XLO   8192
#define Q_HHI   16384
#define Q_HLO   20480
#define QUAD_SZ 24576
#define S_B1    (NQUAD * QUAD_SZ)      // 147456, 64 f32
#define S_B2    (S_B1 + 256)           // 256 f32
#define S_IDX   (S_B2 + 1024)          // 6 ints
#define SMEM_TOTAL (S_IDX + 64)        // 148544

// ---------------- prep kernel ----------------
__global__ void k_prep_w(const float* __restrict__ W1, const float* __restrict__ W2,
                         const int* __restrict__ msk) {
    int i = blockIdx.x * blockDim.x + threadIdx.x;     // 8192 threads
    if (blockIdx.x == 0) {
        __shared__ int bad;
        if (threadIdx.x == 0) { bad = 0; g_work = 0; }
        __syncthreads();
        for (int j = threadIdx.x; j < 1024; j += blockDim.x)
            if ((unsigned)msk[j] > 1u) atomicOr(&bad, 1);
        __syncthreads();
        if (threadIdx.x == 0) g_mask_is_i32 = bad ? 0 : 1;
    }
    if (i < 2048) {                                     // layer1: [n8(8)][ks(8)][lane]
        int lane = i & 31, ks = (i >> 5) & 7, n8 = i >> 8;
        int n  = 8 * n8 + (lane >> 2);
        int k0 = 16 * ks + 2 * (lane & 3);
        float v00 = W1[k0 * HIDDEN + n],       v01 = W1[(k0 + 1) * HIDDEN + n];
        float v10 = W1[(k0 + 8) * HIDDEN + n], v11 = W1[(k0 + 9) * HIDDEN + n];
        __nv_bfloat16 h00 = __float2bfloat16_rn(v00), h01 = __float2bfloat16_rn(v01);
        __nv_bfloat16 h10 = __float2bfloat16_rn(v10), h11 = __float2bfloat16_rn(v11);
        uint4 f;
        f.x = pack_bf2(v00, v01);
        f.y = pack_bf2(v10, v11);
        f.z = pack_bf2(v00 - __bfloat162float(h00), v01 - __bfloat162float(h01));
        f.w = pack_bf2(v10 - __bfloat162float(h10), v11 - __bfloat162float(h11));
        g_w1f[i] = f;
    } else if (i < 2048 + 4096) {                       // layer2: [n8(32)][ks(4)][lane]
        int j = i - 2048;
        int lane = j & 31, ks = (j >> 5) & 3, n8 = j >> 7;
        int n  = 8 * n8 + (lane >> 2);
        int k0 = 16 * ks + 2 * (lane & 3);
        float v00 = W2[k0 * EMBED + n],       v01 = W2[(k0 + 1) * EMBED + n];
        float v10 = W2[(k0 + 8) * EMBED + n], v11 = W2[(k0 + 9) * EMBED + n];
        __nv_bfloat16 h00 = __float2bfloat16_rn(v00), h01 = __float2bfloat16_rn(v01);
        __nv_bfloat16 h10 = __float2bfloat16_rn(v10), h11 = __float2bfloat16_rn(v11);
        uint4 f;
        f.x = pack_bf2(v00, v01);
        f.y = pack_bf2(v10, v11);
        f.z = pack_bf2(v00 - __bfloat162float(h00), v01 - __bfloat162float(h01));
        f.w = pack_bf2(v10 - __bfloat162float(h10), v11 - __bfloat162float(h11));
        g_w2f[j] = f;
    }
}

// ---------------- persistent main kernel: 6 independent 4-warp quad pipelines ----------------
// quad qid grabs 32-row subtiles from a global queue; warp wq = wid&3:
//   layer1 cols 16wq..+15, layer2 cols 64wq..+63 (two 32-col passes), over the quad's 32 rows
__global__ __launch_bounds__(768, 1)
void k_main(const float* __restrict__ x, const int* __restrict__ idx10,
            const float* __restrict__ b1, const float* __restrict__ b2)
{
    extern __shared__ char sm[];
    const uint32_t smb = smem_u32(sm);
    const int tid  = threadIdx.x;
    const int wid  = tid >> 5;
    const int lane = tid & 31;
    const int qid  = wid >> 2;        // quad 0..5
    const int wq   = wid & 3;
    const int tiq  = tid & 127;       // thread-in-quad
    const int q    = lane & 3;
    const int rb   = lane >> 2;
    const int arow  = lane & 15;
    const int acol8 = (lane >> 4) * 8;
    const int barid = qid + 1;

    const uint32_t qb = smb + (uint32_t)qid * QUAD_SZ;
    int* s_idx = (int*)(sm + S_IDX);

    if (tid < 64)  ((float*)(sm + S_B1))[tid] = b1[tid];
    if (tid < 256) ((float*)(sm + S_B2))[tid] = b2[tid];
    if (tiq == 0)  s_idx[qid] = atomicAdd(&g_work, 1);
    __syncthreads();   // biases + initial index visible

    for (;;) {
        const int my = s_idx[qid];
        if (my >= NSUB) break;
        QBAR(barid);                              // everyone has read my
        if (tiq == 0) s_idx[qid] = atomicAdd(&g_work, 1);   // next idx, latency hidden

        // ---- load own 32 rows of x (direct LDG, MLP=8) and convert -> XHI/XLO ----
        {
            float4 v[8];
            #pragma unroll
            for (int j = 0; j < 8; j++) {
                int i = tiq + j * 128;
                v[j] = ((const float4*)x)[(size_t)(my * SUB_M + (i >> 5)) * 32 + (i & 31)];
            }
            #pragma unroll
            for (int j = 0; j < 8; j++) {
                int i = tiq + j * 128;
                int p = i >> 5, c4 = i & 31;
                __nv_bfloat16 h0 = __float2bfloat16_rn(v[j].x), h1 = __float2bfloat16_rn(v[j].y);
                __nv_bfloat16 h2 = __float2bfloat16_rn(v[j].z), h3 = __float2bfloat16_rn(v[j].w);
                uint2 hi = make_uint2(pack_bf2(v[j].x, v[j].y), pack_bf2(v[j].z, v[j].w));
                uint2 lo = make_uint2(
                    pack_bf2(v[j].x - __bfloat162float(h0), v[j].y - __bfloat162float(h1)),
                    pack_bf2(v[j].z - __bfloat162float(h2), v[j].w - __bfloat162float(h3)));
                uint32_t off = off256((uint32_t)p, (uint32_t)(c4 * 4));
                *(uint2*)(sm + qid * QUAD_SZ + Q_XHI + off) = hi;
                *(uint2*)(sm + qid * QUAD_SZ + Q_XLO + off) = lo;
            }
        }
        QBAR(barid);                              // XHI/XLO ready

        // ================= layer 1: 32 rows (mt 0,1), cols 16wq..+15 =================
        float acc[2][2][4];   // [mt][nth][4]
        #pragma unroll
        for (int mt = 0; mt < 2; mt++)
            #pragma unroll
            for (int nth = 0; nth < 2; nth++)
                #pragma unroll
                for (int j = 0; j < 4; j++) acc[mt][nth][j] = 0.f;

        {
            uint32_t ah[2][2][4], al[2][2][4];   // [buf][mt]
            #pragma unroll
            for (int mt = 0; mt < 2; mt++) {
                uint32_t o = off256((uint32_t)(16*mt + arow), (uint32_t)acol8);
                ldsm4(ah[0][mt], qb + Q_XHI + o);
                ldsm4(al[0][mt], qb + Q_XLO + o);
            }
            #pragma unroll
            for (int ks = 0; ks < 8; ks++) {
                const int cur = ks & 1;
                if (ks < 7) {
                    #pragma unroll
                    for (int mt = 0; mt < 2; mt++) {
                        uint32_t o = off256((uint32_t)(16*mt + arow),
                                            (uint32_t)(16*(ks + 1) + acol8));
                        ldsm4(ah[cur ^ 1][mt], qb + Q_XHI + o);
                        ldsm4(al[cur ^ 1][mt], qb + Q_XLO + o);
                    }
                }
                #pragma unroll
                for (int nth = 0; nth < 2; nth++) {
                    const uint4 f = __ldg(&g_w1f[((2*wq + nth)*8 + ks)*32 + lane]);
                    #pragma unroll
                    for (int mt = 0; mt < 2; mt++) {
                        mma_bf16(acc[mt][nth], ah[cur][mt], f.x, f.y);
                        mma_bf16(acc[mt][nth], al[cur][mt], f.x, f.y);
                        mma_bf16(acc[mt][nth], ah[cur][mt], f.z, f.w);
                    }
                }
            }
        }

        // epilogue 1: bias + relu -> bf16 hi/lo into quad H
        {
            const float* b1s = (const float*)(sm + S_B1);
            #pragma unroll
            for (int nth = 0; nth < 2; nth++) {
                const int col = 16*wq + 8*nth + 2*q;
                const float bia0 = b1s[col], bia1 = b1s[col + 1];
                #pragma unroll
                for (int mt = 0; mt < 2; mt++) {
                    int r1 = 16*mt + rb, r2 = r1 + 8;
                    float v00 = fmaxf(acc[mt][nth][0] + bia0, 0.f);
                    float v01 = fmaxf(acc[mt][nth][1] + bia1, 0.f);
                    float v10 = fmaxf(acc[mt][nth][2] + bia0, 0.f);
                    float v11 = fmaxf(acc[mt][nth][3] + bia1, 0.f);
                    __nv_bfloat16 h00 = __float2bfloat16_rn(v00), h01 = __float2bfloat16_rn(v01);
                    __nv_bfloat16 h10 = __float2bfloat16_rn(v10), h11 = __float2bfloat16_rn(v11);
                    uint32_t o1 = off128((uint32_t)r1, (uint32_t)col);
                    uint32_t o2 = off128((uint32_t)r2, (uint32_t)col);
                    *(uint32_t*)(sm + qid * QUAD_SZ + Q_HHI + o1) = pack_bf2(v00, v01);
                    *(uint32_t*)(sm + qid * QUAD_SZ + Q_HHI + o2) = pack_bf2(v10, v11);
                    *(uint32_t*)(sm + qid * QUAD_SZ + Q_HLO + o1) =
                        pack_bf2(v00 - __bfloat162float(h00), v01 - __bfloat162float(h01));
                    *(uint32_t*)(sm + qid * QUAD_SZ + Q_HLO + o2) =
                        pack_bf2(v10 - __bfloat162float(h10), v11 - __bfloat162float(h11));
                }
            }
        }
        QBAR(barid);                              // H ready

        // sp ids for this thread's fragment rows
        int sp0[2], sp1[2];
        #pragma unroll
        for (int mt = 0; mt < 2; mt++) {
            sp0[mt] = idx10[my * SUB_M + 16*mt + rb];
            sp1[mt] = idx10[my * SUB_M + 16*mt + rb + 8];
        }

        // ================= layer 2: 32 rows, cols 64wq..+63, two 32-col passes =================
        const float* b2s = (const float*)(sm + S_B2);
        #pragma unroll 1
        for (int hf = 0; hf < 2; hf++) {
            float a2[4][2][4];   // [ntl][mt][4] = 32 regs
            #pragma unroll
            for (int ntl = 0; ntl < 4; ntl++)
                #pragma unroll
                for (int mt = 0; mt < 2; mt++)
                    #pragma unroll
                    for (int j = 0; j < 4; j++) a2[ntl][mt][j] = 0.f;

            {
                uint32_t ah[2][2][4], al[2][2][4];   // [buf][mt]
                #pragma unroll
                for (int mt = 0; mt < 2; mt++) {
                    uint32_t o = off128((uint32_t)(16*mt + arow), (uint32_t)acol8);
                    ldsm4(ah[0][mt], qb + Q_HHI + o);
                    ldsm4(al[0][mt], qb + Q_HLO + o);
                }
                #pragma unroll
                for (int ks = 0; ks < 4; ks++) {
                    const int cur = ks & 1;
                    if (ks < 3) {
                        #pragma unroll
                        for (int mt = 0; mt < 2; mt++) {
                            uint32_t o = off128((uint32_t)(16*mt + arow),
                                                (uint32_t)(16*(ks + 1) + acol8));
                            ldsm4(ah[cur ^ 1][mt], qb + Q_HHI + o);
                            ldsm4(al[cur ^ 1][mt], qb + Q_HLO + o);
                        }
                    }
                    #pragma unroll
                    for (int ntl = 0; ntl < 4; ntl++) {
                        const uint4 f = __ldg(&g_w2f[((8*wq + 4*hf + ntl)*4 + ks)*32 + lane]);
                        #pragma unroll
                        for (int mt = 0; mt < 2; mt++) {
                            mma_bf16(a2[ntl][mt], ah[cur][mt], f.x, f.y);
                            mma_bf16(a2[ntl][mt], al[cur][mt], f.x, f.y);
                            mma_bf16(a2[ntl][mt], ah[cur][mt], f.z, f.w);
                        }
                    }
                }
            }

            // epilogue 2: bias + relu + 2-row segmented max -> atomicMax
            #pragma unroll
            for (int ntl = 0; ntl < 4; ntl++) {
                int colb = 64*wq + 8*(4*hf + ntl) + 2*q;
                #pragma unroll
                for (int c01 = 0; c01 < 2; c01++) {
                    int col = colb + c01;
                    float bias = b2s[col];
                    #pragma unroll
                    for (int mt = 0; mt < 2; mt++) {
                        float v0 = fmaxf(a2[ntl][mt][c01]     + bias, 0.f);
                        float v1 = fmaxf(a2[ntl][mt][c01 + 2] + bias, 0.f);
                        if (sp0[mt] == sp1[mt]) {
                            atomicMax(&g_tok[sp0[mt] * EMBED + col],
                                      __float_as_int(fmaxf(v0, v1)));
                        } else {
                            atomicMax(&g_tok[sp0[mt] * EMBED + col], __float_as_int(v0));
                            atomicMax(&g_tok[sp1[mt] * EMBED + col], __float_as_int(v1));
                        }
                    }
                }
            }
        }
        // loop-top QBAR (after s_idx read) orders next-iter smem writes after this iter's reads
    }
}

// ---------------- scatter ----------------
__global__ void k_scatter(const int* __restrict__ idx21,
                          const void* __restrict__ is_masked,
                          float* __restrict__ out)
{
    const int sp = blockIdx.x;
    __shared__ int s_off;
    if (threadIdx.x == 0) {
        const int mode = g_mask_is_i32;
        const int* mi = (const int*)is_masked;
        const unsigned char* mb = (const unsigned char*)is_masked;
        int g = idx21[sp];
        int lo = 0, hi = sp;
        while (lo < hi) { int mid = (lo + hi) >> 1; if (idx21[mid] < g) lo = mid + 1; else hi = mid; }
        bool me = mode ? (mi[sp] != 0) : (mb[sp] != 0);
        int rank = 0;
        for (int j = lo; j < sp; j++) {
            bool fj = mode ? (mi[j] != 0) : (mb[j] != 0);
            rank += (fj == me);
        }
        int b = me ? (NUM_SP2 * PAD_LIMIT * EMBED) : 0;
        s_off = b + (g * PAD_LIMIT + rank) * EMBED;
    }
    __syncthreads();
    float4*       dst = (float4*)(out + s_off);
    const float4* src = (const float4*)((const float*)g_tok + sp * EMBED);
    dst[threadIdx.x] = src[threadIdx.x];
}

// ---------------- launch ----------------
extern "C" void kernel_launch(void* const* d_in, const int* in_sizes, int n_in,
                              void* d_out, int out_size) {
    const float* x     = (const float*)d_in[0];
    const int*   idx10 = (const int*)d_in[1];
    const int*   idx21 = (const int*)d_in[2];
    const void*  msk   = (const void*)d_in[3];
    const float* W1    = (const float*)d_in[4];
    const float* b1    = (const float*)d_in[5];
    const float* W2    = (const float*)d_in[6];
    const float* b2    = (const float*)d_in[7];
    float* out = (float*)d_out;

    cudaFuncSetAttribute(k_main, cudaFuncAttributeMaxDynamicSharedMemorySize, SMEM_TOTAL);

    void* tok_ptr = nullptr;
    cudaGetSymbolAddress(&tok_ptr, g_tok);

    cudaMemsetAsync(out, 0, (size_t)out_size * sizeof(float));
    cudaMemsetAsync(tok_ptr, 0, (size_t)NUM_SP * EMBED * sizeof(int));
    k_prep_w<<<32, 256>>>(W1, W2, (const int*)msk);
    k_main<<<GRID_MAIN, 768, SMEM_TOTAL>>>(x, idx10, b1, b2);
    k_scatter<<<NUM_SP, 64>>>(idx21, msk, out);
}

// round 13
// speedup vs baseline: 1.6470x; 1.1554x over previous
#include <cuda_runtime.h>
#include <cuda_fp16.h>
#include <stdint.h>

#define N_POINTS 262144
#define SP_FEAT  128
#define HIDDEN   64
#define EMBED    256
#define NUM_SP   4096
#define NUM_SP2  256
#define PAD_LIMIT 64
#define SUB_M    32
#define NSUB     (N_POINTS / SUB_M)    // 8192
#define GRID_MAIN 148
#define NQUAD    6

// ---------------- device scratch ----------------
__device__ int g_tok[NUM_SP * EMBED];          // float bits, values >= 0
__device__ int g_mask_is_i32;
__device__ int g_work;                         // work queue head (reset by k_prep_w)
// prepacked fp16 B fragments (mma.m16n8k16), uint2 = {reg0, reg1}
__device__ __align__(16) uint2 g_w1f[8 * 8 * 32];    // [n8][ks][lane] (16 KB)
__device__ __align__(16) uint2 g_w2f[32 * 4 * 32];   // [n8][ks][lane] (32 KB)

// ---------------- helpers ----------------
__device__ __forceinline__ uint32_t smem_u32(const void* p) {
    uint32_t a;
    asm("{ .reg .u64 t; cvta.to.shared.u64 t, %1; cvt.u32.u64 %0, t; }" : "=r"(a) : "l"(p));
    return a;
}
__device__ __forceinline__ uint32_t off256(uint32_t row, uint32_t k) {
    return row * 256u + (((k >> 3) ^ (row & 7u)) << 4) + (k & 7u) * 2u;
}
__device__ __forceinline__ uint32_t off128(uint32_t row, uint32_t k) {
    return row * 128u + ((((k >> 3) ^ (row & 7u)) & 7u) << 4) + (k & 7u) * 2u;
}
__device__ __forceinline__ uint32_t pack_hf2(float a, float b) {
    __half2 t = __floats2half2_rn(a, b);       // .x=a (low half)
    return *(uint32_t*)&t;
}
__device__ __forceinline__ void ldsm4(uint32_t r[4], uint32_t addr) {
    asm volatile("ldmatrix.sync.aligned.m8n8.x4.shared.b16 {%0,%1,%2,%3}, [%4];"
                 : "=r"(r[0]), "=r"(r[1]), "=r"(r[2]), "=r"(r[3]) : "r"(addr));
}
__device__ __forceinline__ void mma_f16(float c[4], const uint32_t a[4],
                                        uint32_t b0, uint32_t b1) {
    asm volatile("mma.sync.aligned.m16n8k16.row.col.f32.f16.f16.f32 "
                 "{%0,%1,%2,%3}, {%4,%5,%6,%7}, {%8,%9}, {%0,%1,%2,%3};"
                 : "+f"(c[0]), "+f"(c[1]), "+f"(c[2]), "+f"(c[3])
                 : "r"(a[0]), "r"(a[1]), "r"(a[2]), "r"(a[3]), "r"(b0), "r"(b1));
}
#define QBAR(id) asm volatile("bar.sync %0, 128;" :: "r"(id) : "memory")

// ---------------- smem layout: 6 quad-private arenas ----------------
// per quad (24576 B): XHI 8192 | XLO 8192 | HHI 4096 | HLO 4096
#define Q_XHI   0
#define Q_XLO   8192
#define Q_HHI   16384
#define Q_HLO   20480
#define QUAD_SZ 24576
#define S_B1    (NQUAD * QUAD_SZ)      // 147456, 64 f32
#define S_B2    (S_B1 + 256)           // 256 f32
#define S_IDX   (S_B2 + 1024)          // 6 ints
#define SMEM_TOTAL (S_IDX + 64)        // 148544

// ---------------- prep kernel ----------------
__global__ void k_prep_w(const float* __restrict__ W1, const float* __restrict__ W2,
                         const int* __restrict__ msk) {
    int i = blockIdx.x * blockDim.x + threadIdx.x;     // 8192 threads
    if (blockIdx.x == 0) {
        __shared__ int bad;
        if (threadIdx.x == 0) { bad = 0; g_work = 0; }
        __syncthreads();
        for (int j = threadIdx.x; j < 1024; j += blockDim.x)
            if ((unsigned)msk[j] > 1u) atomicOr(&bad, 1);
        __syncthreads();
        if (threadIdx.x == 0) g_mask_is_i32 = bad ? 0 : 1;
    }
    if (i < 2048) {                                     // layer1: [n8(8)][ks(8)][lane]
        int lane = i & 31, ks = (i >> 5) & 7, n8 = i >> 8;
        int n  = 8 * n8 + (lane >> 2);
        int k0 = 16 * ks + 2 * (lane & 3);
        uint2 f;
        f.x = pack_hf2(W1[k0 * HIDDEN + n],       W1[(k0 + 1) * HIDDEN + n]);
        f.y = pack_hf2(W1[(k0 + 8) * HIDDEN + n], W1[(k0 + 9) * HIDDEN + n]);
        g_w1f[i] = f;
    } else if (i < 2048 + 4096) {                       // layer2: [n8(32)][ks(4)][lane]
        int j = i - 2048;
        int lane = j & 31, ks = (j >> 5) & 3, n8 = j >> 7;
        int n  = 8 * n8 + (lane >> 2);
        int k0 = 16 * ks + 2 * (lane & 3);
        uint2 f;
        f.x = pack_hf2(W2[k0 * EMBED + n],       W2[(k0 + 1) * EMBED + n]);
        f.y = pack_hf2(W2[(k0 + 8) * EMBED + n], W2[(k0 + 9) * EMBED + n]);
        g_w2f[j] = f;
    }
}

// ---------------- persistent main kernel: 6 independent 4-warp quad pipelines ----------------
__global__ __launch_bounds__(768, 1)
void k_main(const float* __restrict__ x, const int* __restrict__ idx10,
            const float* __restrict__ b1, const float* __restrict__ b2)
{
    extern __shared__ char sm[];
    const uint32_t smb = smem_u32(sm);
    const int tid  = threadIdx.x;
    const int wid  = tid >> 5;
    const int lane = tid & 31;
    const int qid  = wid >> 2;        // quad 0..5
    const int wq   = wid & 3;
    const int tiq  = tid & 127;       // thread-in-quad
    const int q    = lane & 3;
    const int rb   = lane >> 2;
    const int arow  = lane & 15;
    const int acol8 = (lane >> 4) * 8;
    const int barid = qid + 1;

    const uint32_t qb = smb + (uint32_t)qid * QUAD_SZ;
    int* s_idx = (int*)(sm + S_IDX);

    if (tid < 64)  ((float*)(sm + S_B1))[tid] = b1[tid];
    if (tid < 256) ((float*)(sm + S_B2))[tid] = b2[tid];
    if (tiq == 0)  s_idx[qid] = atomicAdd(&g_work, 1);
    __syncthreads();   // biases + initial index visible

    for (;;) {
        const int my = s_idx[qid];
        if (my >= NSUB) break;
        QBAR(barid);                              // everyone has read my
        if (tiq == 0) s_idx[qid] = atomicAdd(&g_work, 1);   // next idx, latency hidden

        // ---- load own 32 rows of x (direct LDG, MLP=8), fp16 split -> XHI/XLO ----
        {
            float4 v[8];
            #pragma unroll
            for (int j = 0; j < 8; j++) {
                int i = tiq + j * 128;
                v[j] = ((const float4*)x)[(size_t)(my * SUB_M + (i >> 5)) * 32 + (i & 31)];
            }
            #pragma unroll
            for (int j = 0; j < 8; j++) {
                int i = tiq + j * 128;
                int p = i >> 5, c4 = i & 31;
                __half h0 = __float2half_rn(v[j].x), h1 = __float2half_rn(v[j].y);
                __half h2 = __float2half_rn(v[j].z), h3 = __float2half_rn(v[j].w);
                uint2 hi = make_uint2(pack_hf2(v[j].x, v[j].y), pack_hf2(v[j].z, v[j].w));
                uint2 lo = make_uint2(
                    pack_hf2(v[j].x - __half2float(h0), v[j].y - __half2float(h1)),
                    pack_hf2(v[j].z - __half2float(h2), v[j].w - __half2float(h3)));
                uint32_t off = off256((uint32_t)p, (uint32_t)(c4 * 4));
                *(uint2*)(sm + qid * QUAD_SZ + Q_XHI + off) = hi;
                *(uint2*)(sm + qid * QUAD_SZ + Q_XLO + off) = lo;
            }
        }
        QBAR(barid);                              // XHI/XLO ready

        // ================= layer 1: 32 rows (mt 0,1), cols 16wq..+15 =================
        float acc[2][2][4];   // [mt][nth][4]
        #pragma unroll
        for (int mt = 0; mt < 2; mt++)
            #pragma unroll
            for (int nth = 0; nth < 2; nth++)
                #pragma unroll
                for (int j = 0; j < 4; j++) acc[mt][nth][j] = 0.f;

        {
            uint32_t ah[2][2][4], al[2][2][4];   // [buf][mt]
            #pragma unroll
            for (int mt = 0; mt < 2; mt++) {
                uint32_t o = off256((uint32_t)(16*mt + arow), (uint32_t)acol8);
                ldsm4(ah[0][mt], qb + Q_XHI + o);
                ldsm4(al[0][mt], qb + Q_XLO + o);
            }
            #pragma unroll
            for (int ks = 0; ks < 8; ks++) {
                const int cur = ks & 1;
                if (ks < 7) {
                    #pragma unroll
                    for (int mt = 0; mt < 2; mt++) {
                        uint32_t o = off256((uint32_t)(16*mt + arow),
                                            (uint32_t)(16*(ks + 1) + acol8));
                        ldsm4(ah[cur ^ 1][mt], qb + Q_XHI + o);
                        ldsm4(al[cur ^ 1][mt], qb + Q_XLO + o);
                    }
                }
                #pragma unroll
                for (int nth = 0; nth < 2; nth++) {
                    const uint2 f = __ldg(&g_w1f[((2*wq + nth)*8 + ks)*32 + lane]);
                    #pragma unroll
                    for (int mt = 0; mt < 2; mt++) {
                        mma_f16(acc[mt][nth], ah[cur][mt], f.x, f.y);   // hi*W
                        mma_f16(acc[mt][nth], al[cur][mt], f.x, f.y);   // lo*W
                    }
                }
            }
        }

        // epilogue 1: bias + relu -> fp16 hi/lo into quad H
        {
            const float* b1s = (const float*)(sm + S_B1);
            #pragma unroll
            for (int nth = 0; nth < 2; nth++) {
                const int col = 16*wq + 8*nth + 2*q;
                const float bia0 = b1s[col], bia1 = b1s[col + 1];
                #pragma unroll
                for (int mt = 0; mt < 2; mt++) {
                    int r1 = 16*mt + rb, r2 = r1 + 8;
                    float v00 = fmaxf(acc[mt][nth][0] + bia0, 0.f);
                    float v01 = fmaxf(acc[mt][nth][1] + bia1, 0.f);
                    float v10 = fmaxf(acc[mt][nth][2] + bia0, 0.f);
                    float v11 = fmaxf(acc[mt][nth][3] + bia1, 0.f);
                    __half h00 = __float2half_rn(v00), h01 = __float2half_rn(v01);
                    __half h10 = __float2half_rn(v10), h11 = __float2half_rn(v11);
                    uint32_t o1 = off128((uint32_t)r1, (uint32_t)col);
                    uint32_t o2 = off128((uint32_t)r2, (uint32_t)col);
                    *(uint32_t*)(sm + qid * QUAD_SZ + Q_HHI + o1) = pack_hf2(v00, v01);
                    *(uint32_t*)(sm + qid * QUAD_SZ + Q_HHI + o2) = pack_hf2(v10, v11);
                    *(uint32_t*)(sm + qid * QUAD_SZ + Q_HLO + o1) =
                        pack_hf2(v00 - __half2float(h00), v01 - __half2float(h01));
                    *(uint32_t*)(sm + qid * QUAD_SZ + Q_HLO + o2) =
                        pack_hf2(v10 - __half2float(h10), v11 - __half2float(h11));
                }
            }
        }
        QBAR(barid);                              // H ready

        // sp ids for this thread's fragment rows
        int sp0[2], sp1[2];
        #pragma unroll
        for (int mt = 0; mt < 2; mt++) {
            sp0[mt] = idx10[my * SUB_M + 16*mt + rb];
            sp1[mt] = idx10[my * SUB_M + 16*mt + rb + 8];
        }

        // ================= layer 2: 32 rows, cols 64wq..+63, two 32-col passes =================
        const float* b2s = (const float*)(sm + S_B2);
        #pragma unroll 1
        for (int hf = 0; hf < 2; hf++) {
            float a2[4][2][4];   // [ntl][mt][4] = 32 regs
            #pragma unroll
            for (int ntl = 0; ntl < 4; ntl++)
                #pragma unroll
                for (int mt = 0; mt < 2; mt++)
                    #pragma unroll
                    for (int j = 0; j < 4; j++) a2[ntl][mt][j] = 0.f;

            {
                uint32_t ah[2][2][4], al[2][2][4];   // [buf][mt]
                #pragma unroll
                for (int mt = 0; mt < 2; mt++) {
                    uint32_t o = off128((uint32_t)(16*mt + arow), (uint32_t)acol8);
                    ldsm4(ah[0][mt], qb + Q_HHI + o);
                    ldsm4(al[0][mt], qb + Q_HLO + o);
                }
                #pragma unroll
                for (int ks = 0; ks < 4; ks++) {
                    const int cur = ks & 1;
                    if (ks < 3) {
                        #pragma unroll
                        for (int mt = 0; mt < 2; mt++) {
                            uint32_t o = off128((uint32_t)(16*mt + arow),
                                                (uint32_t)(16*(ks + 1) + acol8));
                            ldsm4(ah[cur ^ 1][mt], qb + Q_HHI + o);
                            ldsm4(al[cur ^ 1][mt], qb + Q_HLO + o);
                        }
                    }
                    #pragma unroll
                    for (int ntl = 0; ntl < 4; ntl++) {
                        const uint2 f = __ldg(&g_w2f[((8*wq + 4*hf + ntl)*4 + ks)*32 + lane]);
                        #pragma unroll
                        for (int mt = 0; mt < 2; mt++) {
                            mma_f16(a2[ntl][mt], ah[cur][mt], f.x, f.y);
                            mma_f16(a2[ntl][mt], al[cur][mt], f.x, f.y);
                        }
                    }
                }
            }

            // epilogue 2: bias + relu + 2-row segmented max -> atomicMax
            #pragma unroll
            for (int ntl = 0; ntl < 4; ntl++) {
                int colb = 64*wq + 8*(4*hf + ntl) + 2*q;
                #pragma unroll
                for (int c01 = 0; c01 < 2; c01++) {
                    int col = colb + c01;
                    float bias = b2s[col];
                    #pragma unroll
                    for (int mt = 0; mt < 2; mt++) {
                        float v0 = fmaxf(a2[ntl][mt][c01]     + bias, 0.f);
                        float v1 = fmaxf(a2[ntl][mt][c01 + 2] + bias, 0.f);
                        if (sp0[mt] == sp1[mt]) {
                            atomicMax(&g_tok[sp0[mt] * EMBED + col],
                                      __float_as_int(fmaxf(v0, v1)));
                        } else {
                            atomicMax(&g_tok[sp0[mt] * EMBED + col], __float_as_int(v0));
                            atomicMax(&g_tok[sp1[mt] * EMBED + col], __float_as_int(v1));
                        }
                    }
                }
            }
        }
        // loop-top QBAR (after s_idx read) orders next-iter smem writes after this iter's reads
    }
}

// ---------------- scatter ----------------
__global__ void k_scatter(const int* __restrict__ idx21,
                          const void* __restrict__ is_masked,
                          float* __restrict__ out)
{
    const int sp = blockIdx.x;
    __shared__ int s_off;
    if (threadIdx.x == 0) {
        const int mode = g_mask_is_i32;
        const int* mi = (const int*)is_masked;
        const unsigned char* mb = (const unsigned char*)is_masked;
        int g = idx21[sp];
        int lo = 0, hi = sp;
        while (lo < hi) { int mid = (lo + hi) >> 1; if (idx21[mid] < g) lo = mid + 1; else hi = mid; }
        bool me = mode ? (mi[sp] != 0) : (mb[sp] != 0);
        int rank = 0;
        for (int j = lo; j < sp; j++) {
            bool fj = mode ? (mi[j] != 0) : (mb[j] != 0);
            rank += (fj == me);
        }
        int b = me ? (NUM_SP2 * PAD_LIMIT * EMBED) : 0;
        s_off = b + (g * PAD_LIMIT + rank) * EMBED;
    }
    __syncthreads();
    float4*       dst = (float4*)(out + s_off);
    const float4* src = (const float4*)((const float*)g_tok + sp * EMBED);
    dst[threadIdx.x] = src[threadIdx.x];
}

// ---------------- launch ----------------
extern "C" void kernel_launch(void* const* d_in, const int* in_sizes, int n_in,
                              void* d_out, int out_size) {
    const float* x     = (const float*)d_in[0];
    const int*   idx10 = (const int*)d_in[1];
    const int*   idx21 = (const int*)d_in[2];
    const void*  msk   = (const void*)d_in[3];
    const float* W1    = (const float*)d_in[4];
    const float* b1    = (const float*)d_in[5];
    const float* W2    = (const float*)d_in[6];
    const float* b2    = (const float*)d_in[7];
    float* out = (float*)d_out;

    cudaFuncSetAttribute(k_main, cudaFuncAttributeMaxDynamicSharedMemorySize, SMEM_TOTAL);

    void* tok_ptr = nullptr;
    cudaGetSymbolAddress(&tok_ptr, g_tok);

    cudaMemsetAsync(out, 0, (size_t)out_size * sizeof(float));
    cudaMemsetAsync(tok_ptr, 0, (size_t)NUM_SP * EMBED * sizeof(int));
    k_prep_w<<<32, 256>>>(W1, W2, (const int*)msk);
    k_main<<<GRID_MAIN, 768, SMEM_TOTAL>>>(x, idx10, b1, b2);
    k_scatter<<<NUM_SP, 64>>>(idx21, msk, out);
}

// round 14
// speedup vs baseline: 1.9213x; 1.1666x over previous
#include <cuda_runtime.h>
#include <cuda_fp16.h>
#include <stdint.h>

#define N_POINTS 262144
#define SP_FEAT  128
#define HIDDEN   64
#define EMBED    256
#define NUM_SP   4096
#define NUM_SP2  256
#define PAD_LIMIT 64
#define SUB_M    32
#define NSUB     (N_POINTS / SUB_M)    // 8192
#define GRID_MAIN 148
#define NQUAD    6

// ---------------- device scratch ----------------
__device__ int g_tok[NUM_SP * EMBED];          // float bits, values >= 0
__device__ int g_mask_is_i32;
__device__ int g_work;                         // work queue head (reset by k_prep_w)
// prepacked fp16 B fragments (mma.m16n8k16), uint2 = {reg0, reg1}
__device__ __align__(16) uint2 g_w1f[8 * 8 * 32];    // [n8][ks][lane] (16 KB)
__device__ __align__(16) uint2 g_w2f[32 * 4 * 32];   // [n8][ks][lane] (32 KB)

// ---------------- helpers ----------------
__device__ __forceinline__ uint32_t smem_u32(const void* p) {
    uint32_t a;
    asm("{ .reg .u64 t; cvta.to.shared.u64 t, %1; cvt.u32.u64 %0, t; }" : "=r"(a) : "l"(p));
    return a;
}
__device__ __forceinline__ uint32_t off256(uint32_t row, uint32_t k) {
    return row * 256u + (((k >> 3) ^ (row & 7u)) << 4) + (k & 7u) * 2u;
}
__device__ __forceinline__ uint32_t off128(uint32_t row, uint32_t k) {
    return row * 128u + ((((k >> 3) ^ (row & 7u)) & 7u) << 4) + (k & 7u) * 2u;
}
__device__ __forceinline__ uint32_t pack_hf2(float a, float b) {
    __half2 t = __floats2half2_rn(a, b);       // .x=a (low half)
    return *(uint32_t*)&t;
}
__device__ __forceinline__ void ldsm4(uint32_t r[4], uint32_t addr) {
    asm volatile("ldmatrix.sync.aligned.m8n8.x4.shared.b16 {%0,%1,%2,%3}, [%4];"
                 : "=r"(r[0]), "=r"(r[1]), "=r"(r[2]), "=r"(r[3]) : "r"(addr));
}
__device__ __forceinline__ void mma_f16(float c[4], const uint32_t a[4],
                                        uint32_t b0, uint32_t b1) {
    asm volatile("mma.sync.aligned.m16n8k16.row.col.f32.f16.f16.f32 "
                 "{%0,%1,%2,%3}, {%4,%5,%6,%7}, {%8,%9}, {%0,%1,%2,%3};"
                 : "+f"(c[0]), "+f"(c[1]), "+f"(c[2]), "+f"(c[3])
                 : "r"(a[0]), "r"(a[1]), "r"(a[2]), "r"(a[3]), "r"(b0), "r"(b1));
}
#define QBAR(id) asm volatile("bar.sync %0, 128;" :: "r"(id) : "memory")

// ---------------- smem layout: 6 quad-private arenas ----------------
// per quad (12288 B): XF 8192 (32x128 fp16, 256B rows) | HF 4096 (32x64 fp16, 128B rows)
#define Q_XF    0
#define Q_HF    8192
#define QUAD_SZ 12288
#define S_B1    (NQUAD * QUAD_SZ)      // 73728, 64 f32
#define S_B2    (S_B1 + 256)           // 256 f32
#define S_IDX   (S_B2 + 1024)          // 6 ints
#define SMEM_TOTAL (S_IDX + 64)        // 74816

// ---------------- prep kernel ----------------
__global__ void k_prep_w(const float* __restrict__ W1, const float* __restrict__ W2,
                         const int* __restrict__ msk) {
    int i = blockIdx.x * blockDim.x + threadIdx.x;     // 8192 threads
    if (blockIdx.x == 0) {
        __shared__ int bad;
        if (threadIdx.x == 0) { bad = 0; g_work = 0; }
        __syncthreads();
        for (int j = threadIdx.x; j < 1024; j += blockDim.x)
            if ((unsigned)msk[j] > 1u) atomicOr(&bad, 1);
        __syncthreads();
        if (threadIdx.x == 0) g_mask_is_i32 = bad ? 0 : 1;
    }
    if (i < 2048) {                                     // layer1: [n8(8)][ks(8)][lane]
        int lane = i & 31, ks = (i >> 5) & 7, n8 = i >> 8;
        int n  = 8 * n8 + (lane >> 2);
        int k0 = 16 * ks + 2 * (lane & 3);
        uint2 f;
        f.x = pack_hf2(W1[k0 * HIDDEN + n],       W1[(k0 + 1) * HIDDEN + n]);
        f.y = pack_hf2(W1[(k0 + 8) * HIDDEN + n], W1[(k0 + 9) * HIDDEN + n]);
        g_w1f[i] = f;
    } else if (i < 2048 + 4096) {                       // layer2: [n8(32)][ks(4)][lane]
        int j = i - 2048;
        int lane = j & 31, ks = (j >> 5) & 3, n8 = j >> 7;
        int n  = 8 * n8 + (lane >> 2);
        int k0 = 16 * ks + 2 * (lane & 3);
        uint2 f;
        f.x = pack_hf2(W2[k0 * EMBED + n],       W2[(k0 + 1) * EMBED + n]);
        f.y = pack_hf2(W2[(k0 + 8) * EMBED + n], W2[(k0 + 9) * EMBED + n]);
        g_w2f[j] = f;
    }
}

// ---------------- persistent main kernel: 6 independent 4-warp quad pipelines ----------------
// quad qid pulls 32-row subtiles off a global queue; warp wq = wid&3:
//   layer1 cols 16wq..+15, layer2 cols 64wq..+63 (two 32-col passes)
__global__ __launch_bounds__(768, 1)
void k_main(const float* __restrict__ x, const int* __restrict__ idx10,
            const float* __restrict__ b1, const float* __restrict__ b2)
{
    extern __shared__ char sm[];
    const uint32_t smb = smem_u32(sm);
    const int tid  = threadIdx.x;
    const int wid  = tid >> 5;
    const int lane = tid & 31;
    const int qid  = wid >> 2;        // quad 0..5
    const int wq   = wid & 3;
    const int tiq  = tid & 127;       // thread-in-quad
    const int q    = lane & 3;
    const int rb   = lane >> 2;
    const int arow  = lane & 15;
    const int acol8 = (lane >> 4) * 8;
    const int barid = qid + 1;

    const uint32_t qb = smb + (uint32_t)qid * QUAD_SZ;
    int* s_idx = (int*)(sm + S_IDX);

    if (tid < 64)  ((float*)(sm + S_B1))[tid] = b1[tid];
    if (tid < 256) ((float*)(sm + S_B2))[tid] = b2[tid];
    if (tiq == 0)  s_idx[qid] = atomicAdd(&g_work, 1);
    __syncthreads();   // biases + initial index visible

    for (;;) {
        const int my = s_idx[qid];
        if (my >= NSUB) break;
        QBAR(barid);                              // everyone has read my
        if (tiq == 0) s_idx[qid] = atomicAdd(&g_work, 1);   // next idx, latency hidden

        // ---- load own 32 rows of x (direct LDG, MLP=8), fp16 round -> XF ----
        {
            float4 v[8];
            #pragma unroll
            for (int j = 0; j < 8; j++) {
                int i = tiq + j * 128;
                v[j] = ((const float4*)x)[(size_t)(my * SUB_M + (i >> 5)) * 32 + (i & 31)];
            }
            #pragma unroll
            for (int j = 0; j < 8; j++) {
                int i = tiq + j * 128;
                int p = i >> 5, c4 = i & 31;
                uint2 hf = make_uint2(pack_hf2(v[j].x, v[j].y), pack_hf2(v[j].z, v[j].w));
                uint32_t off = off256((uint32_t)p, (uint32_t)(c4 * 4));
                *(uint2*)(sm + qid * QUAD_SZ + Q_XF + off) = hf;
            }
        }
        QBAR(barid);                              // XF ready

        // ================= layer 1: 32 rows (mt 0,1), cols 16wq..+15 =================
        float acc[2][2][4];   // [mt][nth][4]
        #pragma unroll
        for (int mt = 0; mt < 2; mt++)
            #pragma unroll
            for (int nth = 0; nth < 2; nth++)
                #pragma unroll
                for (int j = 0; j < 4; j++) acc[mt][nth][j] = 0.f;

        {
            uint32_t af[2][2][4];   // [buf][mt]
            #pragma unroll
            for (int mt = 0; mt < 2; mt++) {
                uint32_t o = off256((uint32_t)(16*mt + arow), (uint32_t)acol8);
                ldsm4(af[0][mt], qb + Q_XF + o);
            }
            #pragma unroll
            for (int ks = 0; ks < 8; ks++) {
                const int cur = ks & 1;
                if (ks < 7) {
                    #pragma unroll
                    for (int mt = 0; mt < 2; mt++) {
                        uint32_t o = off256((uint32_t)(16*mt + arow),
                                            (uint32_t)(16*(ks + 1) + acol8));
                        ldsm4(af[cur ^ 1][mt], qb + Q_XF + o);
                    }
                }
                #pragma unroll
                for (int nth = 0; nth < 2; nth++) {
                    const uint2 f = __ldg(&g_w1f[((2*wq + nth)*8 + ks)*32 + lane]);
                    #pragma unroll
                    for (int mt = 0; mt < 2; mt++)
                        mma_f16(acc[mt][nth], af[cur][mt], f.x, f.y);
                }
            }
        }

        // epilogue 1: bias + relu -> fp16 into quad HF
        {
            const float* b1s = (const float*)(sm + S_B1);
            #pragma unroll
            for (int nth = 0; nth < 2; nth++) {
                const int col = 16*wq + 8*nth + 2*q;
                const float bia0 = b1s[col], bia1 = b1s[col + 1];
                #pragma unroll
                for (int mt = 0; mt < 2; mt++) {
                    int r1 = 16*mt + rb, r2 = r1 + 8;
                    float v00 = fmaxf(acc[mt][nth][0] + bia0, 0.f);
                    float v01 = fmaxf(acc[mt][nth][1] + bia1, 0.f);
                    float v10 = fmaxf(acc[mt][nth][2] + bia0, 0.f);
                    float v11 = fmaxf(acc[mt][nth][3] + bia1, 0.f);
                    *(uint32_t*)(sm + qid * QUAD_SZ + Q_HF + off128((uint32_t)r1, (uint32_t)col))
                        = pack_hf2(v00, v01);
                    *(uint32_t*)(sm + qid * QUAD_SZ + Q_HF + off128((uint32_t)r2, (uint32_t)col))
                        = pack_hf2(v10, v11);
                }
            }
        }
        QBAR(barid);                              // HF ready

        // sp ids for this thread's fragment rows
        int sp0[2], sp1[2];
        #pragma unroll
        for (int mt = 0; mt < 2; mt++) {
            sp0[mt] = idx10[my * SUB_M + 16*mt + rb];
            sp1[mt] = idx10[my * SUB_M + 16*mt + rb + 8];
        }

        // ================= layer 2: 32 rows, cols 64wq..+63, two 32-col passes =================
        const float* b2s = (const float*)(sm + S_B2);
        #pragma unroll 1
        for (int hf = 0; hf < 2; hf++) {
            float a2[4][2][4];   // [ntl][mt][4] = 32 regs
            #pragma unroll
            for (int ntl = 0; ntl < 4; ntl++)
                #pragma unroll
                for (int mt = 0; mt < 2; mt++)
                    #pragma unroll
                    for (int j = 0; j < 4; j++) a2[ntl][mt][j] = 0.f;

            {
                uint32_t af[2][2][4];   // [buf][mt]
                #pragma unroll
                for (int mt = 0; mt < 2; mt++) {
                    uint32_t o = off128((uint32_t)(16*mt + arow), (uint32_t)acol8);
                    ldsm4(af[0][mt], qb + Q_HF + o);
                }
                #pragma unroll
                for (int ks = 0; ks < 4; ks++) {
                    const int cur = ks & 1;
                    if (ks < 3) {
                        #pragma unroll
                        for (int mt = 0; mt < 2; mt++) {
                            uint32_t o = off128((uint32_t)(16*mt + arow),
                                                (uint32_t)(16*(ks + 1) + acol8));
                            ldsm4(af[cur ^ 1][mt], qb + Q_HF + o);
                        }
                    }
                    #pragma unroll
                    for (int ntl = 0; ntl < 4; ntl++) {
                        const uint2 f = __ldg(&g_w2f[((8*wq + 4*hf + ntl)*4 + ks)*32 + lane]);
                        #pragma unroll
                        for (int mt = 0; mt < 2; mt++)
                            mma_f16(a2[ntl][mt], af[cur][mt], f.x, f.y);
                    }
                }
            }

            // epilogue 2: bias + relu + 2-row segmented max -> atomicMax
            #pragma unroll
            for (int ntl = 0; ntl < 4; ntl++) {
                int colb = 64*wq + 8*(4*hf + ntl) + 2*q;
                #pragma unroll
                for (int c01 = 0; c01 < 2; c01++) {
                    int col = colb + c01;
                    float bias = b2s[col];
                    #pragma unroll
                    for (int mt = 0; mt < 2; mt++) {
                        float v0 = fmaxf(a2[ntl][mt][c01]     + bias, 0.f);
                        float v1 = fmaxf(a2[ntl][mt][c01 + 2] + bias, 0.f);
                        if (sp0[mt] == sp1[mt]) {
                            atomicMax(&g_tok[sp0[mt] * EMBED + col],
                                      __float_as_int(fmaxf(v0, v1)));
                        } else {
                            atomicMax(&g_tok[sp0[mt] * EMBED + col], __float_as_int(v0));
                            atomicMax(&g_tok[sp1[mt] * EMBED + col], __float_as_int(v1));
                        }
                    }
                }
            }
        }
        // loop-top QBAR (after s_idx read) orders next-iter smem writes after this iter's reads
    }
}

// ---------------- scatter ----------------
__global__ void k_scatter(const int* __restrict__ idx21,
                          const void* __restrict__ is_masked,
                          float* __restrict__ out)
{
    const int sp = blockIdx.x;
    __shared__ int s_off;
    if (threadIdx.x == 0) {
        const int mode = g_mask_is_i32;
        const int* mi = (const int*)is_masked;
        const unsigned char* mb = (const unsigned char*)is_masked;
        int g = idx21[sp];
        int lo = 0, hi = sp;
        while (lo < hi) { int mid = (lo + hi) >> 1; if (idx21[mid] < g) lo = mid + 1; else hi = mid; }
        bool me = mode ? (mi[sp] != 0) : (mb[sp] != 0);
        int rank = 0;
        for (int j = lo; j < sp; j++) {
            bool fj = mode ? (mi[j] != 0) : (mb[j] != 0);
            rank += (fj == me);
        }
        int b = me ? (NUM_SP2 * PAD_LIMIT * EMBED) : 0;
        s_off = b + (g * PAD_LIMIT + rank) * EMBED;
    }
    __syncthreads();
    float4*       dst = (float4*)(out + s_off);
    const float4* src = (const float4*)((const float*)g_tok + sp * EMBED);
    dst[threadIdx.x] = src[threadIdx.x];
}

// ---------------- launch ----------------
extern "C" void kernel_launch(void* const* d_in, const int* in_sizes, int n_in,
                              void* d_out, int out_size) {
    const float* x     = (const float*)d_in[0];
    const int*   idx10 = (const int*)d_in[1];
    const int*   idx21 = (const int*)d_in[2];
    const void*  msk   = (const void*)d_in[3];
    const float* W1    = (const float*)d_in[4];
    const float* b1    = (const float*)d_in[5];
    const float* W2    = (const float*)d_in[6];
    const float* b2    = (const float*)d_in[7];
    float* out = (float*)d_out;

    cudaFuncSetAttribute(k_main, cudaFuncAttributeMaxDynamicSharedMemorySize, SMEM_TOTAL);

    void* tok_ptr = nullptr;
    cudaGetSymbolAddress(&tok_ptr, g_tok);

    cudaMemsetAsync(out, 0, (size_t)out_size * sizeof(float));
    cudaMemsetAsync(tok_ptr, 0, (size_t)NUM_SP * EMBED * sizeof(int));
    k_prep_w<<<32, 256>>>(W1, W2, (const int*)msk);
    k_main<<<GRID_MAIN, 768, SMEM_TOTAL>>>(x, idx10, b1, b2);
    k_scatter<<<NUM_SP, 64>>>(idx21, msk, out);
}

// round 15
// speedup vs baseline: 1.9774x; 1.0292x over previous
#include <cuda_runtime.h>
#include <cuda_fp16.h>
#include <stdint.h>

#define N_POINTS 262144
#define SP_FEAT  128
#define HIDDEN   64
#define EMBED    256
#define NUM_SP   4096
#define NUM_SP2  256
#define PAD_LIMIT 64
#define SUB_M    32
#define NSUB     (N_POINTS / SUB_M)    // 8192
#define GRID_MAIN 148
#define NQUAD    6

// ---------------- device scratch ----------------
__device__ int g_tok[NUM_SP * EMBED];          // float bits, values >= 0
__device__ int g_mask_is_i32;
__device__ int g_work;                         // work queue head (reset by k_prep_w)
// prepacked fp16 B fragments (mma.m16n8k16), uint2 = {reg0, reg1}
__device__ __align__(16) uint2 g_w1f[8 * 8 * 32];    // [n8][ks][lane] (16 KB)
__device__ __align__(16) uint2 g_w2f[32 * 4 * 32];   // [n8][ks][lane] (32 KB)

// ---------------- helpers ----------------
__device__ __forceinline__ uint32_t smem_u32(const void* p) {
    uint32_t a;
    asm("{ .reg .u64 t; cvta.to.shared.u64 t, %1; cvt.u32.u64 %0, t; }" : "=r"(a) : "l"(p));
    return a;
}
__device__ __forceinline__ uint32_t off256(uint32_t row, uint32_t k) {
    return row * 256u + (((k >> 3) ^ (row & 7u)) << 4) + (k & 7u) * 2u;
}
__device__ __forceinline__ uint32_t off128(uint32_t row, uint32_t k) {
    return row * 128u + ((((k >> 3) ^ (row & 7u)) & 7u) << 4) + (k & 7u) * 2u;
}
__device__ __forceinline__ uint32_t pack_hf2(float a, float b) {
    __half2 t = __floats2half2_rn(a, b);       // .x=a (low half)
    return *(uint32_t*)&t;
}
__device__ __forceinline__ void ldsm4(uint32_t r[4], uint32_t addr) {
    asm volatile("ldmatrix.sync.aligned.m8n8.x4.shared.b16 {%0,%1,%2,%3}, [%4];"
                 : "=r"(r[0]), "=r"(r[1]), "=r"(r[2]), "=r"(r[3]) : "r"(addr));
}
__device__ __forceinline__ uint2 lds64(uint32_t addr) {
    uint2 r;
    asm volatile("ld.shared.v2.b32 {%0,%1}, [%2];" : "=r"(r.x), "=r"(r.y) : "r"(addr));
    return r;
}
__device__ __forceinline__ void mma_f16(float c[4], const uint32_t a[4],
                                        uint32_t b0, uint32_t b1) {
    asm volatile("mma.sync.aligned.m16n8k16.row.col.f32.f16.f16.f32 "
                 "{%0,%1,%2,%3}, {%4,%5,%6,%7}, {%8,%9}, {%0,%1,%2,%3};"
                 : "+f"(c[0]), "+f"(c[1]), "+f"(c[2]), "+f"(c[3])
                 : "r"(a[0]), "r"(a[1]), "r"(a[2]), "r"(a[3]), "r"(b0), "r"(b1));
}
#define QBAR(id) asm volatile("bar.sync %0, 128;" :: "r"(id) : "memory")

// ---------------- smem layout ----------------
// per quad (12288 B): XF 8192 (32x128 fp16) | HF 4096 (32x64 fp16)
#define Q_XF    0
#define Q_HF    8192
#define QUAD_SZ 12288
#define S_W1F   (NQUAD * QUAD_SZ)      // 73728, 16384 B
#define S_W2F   (S_W1F + 16384)        // 90112, 32768 B
#define S_B1    (S_W2F + 32768)        // 122880, 64 f32
#define S_B2    (S_B1 + 256)           // 256 f32
#define S_IDX   (S_B2 + 1024)          // 6 ints
#define SMEM_TOTAL (S_IDX + 64)        // 124224

// ---------------- prep kernel ----------------
__global__ void k_prep_w(const float* __restrict__ W1, const float* __restrict__ W2,
                         const int* __restrict__ msk) {
    int i = blockIdx.x * blockDim.x + threadIdx.x;     // 8192 threads
    if (blockIdx.x == 0) {
        __shared__ int bad;
        if (threadIdx.x == 0) { bad = 0; g_work = 0; }
        __syncthreads();
        for (int j = threadIdx.x; j < 1024; j += blockDim.x)
            if ((unsigned)msk[j] > 1u) atomicOr(&bad, 1);
        __syncthreads();
        if (threadIdx.x == 0) g_mask_is_i32 = bad ? 0 : 1;
    }
    if (i < 2048) {                                     // layer1: [n8(8)][ks(8)][lane]
        int lane = i & 31, ks = (i >> 5) & 7, n8 = i >> 8;
        int n  = 8 * n8 + (lane >> 2);
        int k0 = 16 * ks + 2 * (lane & 3);
        uint2 f;
        f.x = pack_hf2(W1[k0 * HIDDEN + n],       W1[(k0 + 1) * HIDDEN + n]);
        f.y = pack_hf2(W1[(k0 + 8) * HIDDEN + n], W1[(k0 + 9) * HIDDEN + n]);
        g_w1f[i] = f;
    } else if (i < 2048 + 4096) {                       // layer2: [n8(32)][ks(4)][lane]
        int j = i - 2048;
        int lane = j & 31, ks = (j >> 5) & 3, n8 = j >> 7;
        int n  = 8 * n8 + (lane >> 2);
        int k0 = 16 * ks + 2 * (lane & 3);
        uint2 f;
        f.x = pack_hf2(W2[k0 * EMBED + n],       W2[(k0 + 1) * EMBED + n]);
        f.y = pack_hf2(W2[(k0 + 8) * EMBED + n], W2[(k0 + 9) * EMBED + n]);
        g_w2f[j] = f;
    }
}

// ---------------- persistent main kernel: 6 independent 4-warp quad pipelines ----------------
__global__ __launch_bounds__(768, 1)
void k_main(const float* __restrict__ x, const int* __restrict__ idx10,
            const float* __restrict__ b1, const float* __restrict__ b2)
{
    extern __shared__ char sm[];
    const uint32_t smb = smem_u32(sm);
    const int tid  = threadIdx.x;
    const int wid  = tid >> 5;
    const int lane = tid & 31;
    const int qid  = wid >> 2;        // quad 0..5
    const int wq   = wid & 3;
    const int tiq  = tid & 127;       // thread-in-quad
    const int q    = lane & 3;
    const int rb   = lane >> 2;
    const int arow  = lane & 15;
    const int acol8 = (lane >> 4) * 8;
    const int barid = qid + 1;

    const uint32_t qb = smb + (uint32_t)qid * QUAD_SZ;
    int* s_idx = (int*)(sm + S_IDX);

    // copy B-fragment tables into smem (48 KB, L2-hot; immune to x-stream eviction)
    {
        uint4*       d1 = (uint4*)(sm + S_W1F);
        const uint4* s1 = (const uint4*)g_w1f;
        for (int i = tid; i < 1024; i += 768) d1[i] = s1[i];
        uint4*       d2 = (uint4*)(sm + S_W2F);
        const uint4* s2 = (const uint4*)g_w2f;
        for (int i = tid; i < 2048; i += 768) d2[i] = s2[i];
    }
    if (tid < 64)  ((float*)(sm + S_B1))[tid] = b1[tid];
    if (tid < 256) ((float*)(sm + S_B2))[tid] = b2[tid];
    if (tiq == 0)  s_idx[qid] = atomicAdd(&g_work, 1);
    __syncthreads();   // tables + biases + initial index visible

    const uint32_t w1b = smb + S_W1F;
    const uint32_t w2b = smb + S_W2F;

    for (;;) {
        const int my = s_idx[qid];
        if (my >= NSUB) break;
        QBAR(barid);                              // everyone has read my
        if (tiq == 0) s_idx[qid] = atomicAdd(&g_work, 1);   // next idx, latency hidden

        // ---- load own 32 rows of x (streaming LDG, MLP=8), fp16 round -> XF ----
        {
            float4 v[8];
            #pragma unroll
            for (int j = 0; j < 8; j++) {
                int i = tiq + j * 128;
                v[j] = __ldcs(((const float4*)x) +
                              (size_t)(my * SUB_M + (i >> 5)) * 32 + (i & 31));
            }
            #pragma unroll
            for (int j = 0; j < 8; j++) {
                int i = tiq + j * 128;
                int p = i >> 5, c4 = i & 31;
                uint2 hf = make_uint2(pack_hf2(v[j].x, v[j].y), pack_hf2(v[j].z, v[j].w));
                uint32_t off = off256((uint32_t)p, (uint32_t)(c4 * 4));
                *(uint2*)(sm + qid * QUAD_SZ + Q_XF + off) = hf;
            }
        }
        QBAR(barid);                              // XF ready

        // ================= layer 1: 32 rows (mt 0,1), cols 16wq..+15 =================
        float acc[2][2][4];   // [mt][nth][4]
        #pragma unroll
        for (int mt = 0; mt < 2; mt++)
            #pragma unroll
            for (int nth = 0; nth < 2; nth++)
                #pragma unroll
                for (int j = 0; j < 4; j++) acc[mt][nth][j] = 0.f;

        {
            uint32_t af[2][2][4];   // [buf][mt]
            #pragma unroll
            for (int mt = 0; mt < 2; mt++) {
                uint32_t o = off256((uint32_t)(16*mt + arow), (uint32_t)acol8);
                ldsm4(af[0][mt], qb + Q_XF + o);
            }
            #pragma unroll
            for (int ks = 0; ks < 8; ks++) {
                const int cur = ks & 1;
                if (ks < 7) {
                    #pragma unroll
                    for (int mt = 0; mt < 2; mt++) {
                        uint32_t o = off256((uint32_t)(16*mt + arow),
                                            (uint32_t)(16*(ks + 1) + acol8));
                        ldsm4(af[cur ^ 1][mt], qb + Q_XF + o);
                    }
                }
                #pragma unroll
                for (int nth = 0; nth < 2; nth++) {
                    const uint2 f = lds64(w1b + (((2*wq + nth)*8 + ks)*32 + lane) * 8);
                    #pragma unroll
                    for (int mt = 0; mt < 2; mt++)
                        mma_f16(acc[mt][nth], af[cur][mt], f.x, f.y);
                }
            }
        }

        // epilogue 1: bias + relu -> fp16 into quad HF
        {
            const float* b1s = (const float*)(sm + S_B1);
            #pragma unroll
            for (int nth = 0; nth < 2; nth++) {
                const int col = 16*wq + 8*nth + 2*q;
                const float bia0 = b1s[col], bia1 = b1s[col + 1];
                #pragma unroll
                for (int mt = 0; mt < 2; mt++) {
                    int r1 = 16*mt + rb, r2 = r1 + 8;
                    float v00 = fmaxf(acc[mt][nth][0] + bia0, 0.f);
                    float v01 = fmaxf(acc[mt][nth][1] + bia1, 0.f);
                    float v10 = fmaxf(acc[mt][nth][2] + bia0, 0.f);
                    float v11 = fmaxf(acc[mt][nth][3] + bia1, 0.f);
                    *(uint32_t*)(sm + qid * QUAD_SZ + Q_HF + off128((uint32_t)r1, (uint32_t)col))
                        = pack_hf2(v00, v01);
                    *(uint32_t*)(sm + qid * QUAD_SZ + Q_HF + off128((uint32_t)r2, (uint32_t)col))
                        = pack_hf2(v10, v11);
                }
            }
        }
        QBAR(barid);                              // HF ready

        // sp ids for this thread's fragment rows
        int sp0[2], sp1[2];
        #pragma unroll
        for (int mt = 0; mt < 2; mt++) {
            sp0[mt] = idx10[my * SUB_M + 16*mt + rb];
            sp1[mt] = idx10[my * SUB_M + 16*mt + rb + 8];
        }

        // ================= layer 2: 32 rows, cols 64wq..+63, two 32-col passes =================
        const float* b2s = (const float*)(sm + S_B2);
        #pragma unroll 1
        for (int hf = 0; hf < 2; hf++) {
            float a2[4][2][4];   // [ntl][mt][4] = 32 regs
            #pragma unroll
            for (int ntl = 0; ntl < 4; ntl++)
                #pragma unroll
                for (int mt = 0; mt < 2; mt++)
                    #pragma unroll
                    for (int j = 0; j < 4; j++) a2[ntl][mt][j] = 0.f;

            {
                uint32_t af[2][2][4];   // [buf][mt]
                #pragma unroll
                for (int mt = 0; mt < 2; mt++) {
                    uint32_t o = off128((uint32_t)(16*mt + arow), (uint32_t)acol8);
                    ldsm4(af[0][mt], qb + Q_HF + o);
                }
                #pragma unroll
                for (int ks = 0; ks < 4; ks++) {
                    const int cur = ks & 1;
                    if (ks < 3) {
                        #pragma unroll
                        for (int mt = 0; mt < 2; mt++) {
                            uint32_t o = off128((uint32_t)(16*mt + arow),
                                                (uint32_t)(16*(ks + 1) + acol8));
                            ldsm4(af[cur ^ 1][mt], qb + Q_HF + o);
                        }
                    }
                    #pragma unroll
                    for (int ntl = 0; ntl < 4; ntl++) {
                        const uint2 f = lds64(w2b + (((8*wq + 4*hf + ntl)*4 + ks)*32 + lane) * 8);
                        #pragma unroll
                        for (int mt = 0; mt < 2; mt++)
                            mma_f16(a2[ntl][mt], af[cur][mt], f.x, f.y);
                    }
                }
            }

            // epilogue 2: bias + relu + 2-row segmented max -> atomicMax
            #pragma unroll
            for (int ntl = 0; ntl < 4; ntl++) {
                int colb = 64*wq + 8*(4*hf + ntl) + 2*q;
                #pragma unroll
                for (int c01 = 0; c01 < 2; c01++) {
                    int col = colb + c01;
                    float bias = b2s[col];
                    #pragma unroll
                    for (int mt = 0; mt < 2; mt++) {
                        float v0 = fmaxf(a2[ntl][mt][c01]     + bias, 0.f);
                        float v1 = fmaxf(a2[ntl][mt][c01 + 2] + bias, 0.f);
                        if (sp0[mt] == sp1[mt]) {
                            atomicMax(&g_tok[sp0[mt] * EMBED + col],
                                      __float_as_int(fmaxf(v0, v1)));
                        } else {
                            atomicMax(&g_tok[sp0[mt] * EMBED + col], __float_as_int(v0));
                            atomicMax(&g_tok[sp1[mt] * EMBED + col], __float_as_int(v1));
                        }
                    }
                }
            }
        }
        // loop-top QBAR (after s_idx read) orders next-iter smem writes after this iter's reads
    }
}

// ---------------- scatter ----------------
__global__ void k_scatter(const int* __restrict__ idx21,
                          const void* __restrict__ is_masked,
                          float* __restrict__ out)
{
    const int sp = blockIdx.x;
    __shared__ int s_off;
    if (threadIdx.x == 0) {
        const int mode = g_mask_is_i32;
        const int* mi = (const int*)is_masked;
        const unsigned char* mb = (const unsigned char*)is_masked;
        int g = idx21[sp];
        int lo = 0, hi = sp;
        while (lo < hi) { int mid = (lo + hi) >> 1; if (idx21[mid] < g) lo = mid + 1; else hi = mid; }
        bool me = mode ? (mi[sp] != 0) : (mb[sp] != 0);
        int rank = 0;
        for (int j = lo; j < sp; j++) {
            bool fj = mode ? (mi[j] != 0) : (mb[j] != 0);
            rank += (fj == me);
        }
        int b = me ? (NUM_SP2 * PAD_LIMIT * EMBED) : 0;
        s_off = b + (g * PAD_LIMIT + rank) * EMBED;
    }
    __syncthreads();
    float4*       dst = (float4*)(out + s_off);
    const float4* src = (const float4*)((const float*)g_tok + sp * EMBED);
    dst[threadIdx.x] = src[threadIdx.x];
}

// ---------------- launch ----------------
extern "C" void kernel_launch(void* const* d_in, const int* in_sizes, int n_in,
                              void* d_out, int out_size) {
    const float* x     = (const float*)d_in[0];
    const int*   idx10 = (const int*)d_in[1];
    const int*   idx21 = (const int*)d_in[2];
    const void*  msk   = (const void*)d_in[3];
    const float* W1    = (const float*)d_in[4];
    const float* b1    = (const float*)d_in[5];
    const float* W2    = (const float*)d_in[6];
    const float* b2    = (const float*)d_in[7];
    float* out = (float*)d_out;

    cudaFuncSetAttribute(k_main, cudaFuncAttributeMaxDynamicSharedMemorySize, SMEM_TOTAL);

    void* tok_ptr = nullptr;
    cudaGetSymbolAddress(&tok_ptr, g_tok);

    cudaMemsetAsync(out, 0, (size_t)out_size * sizeof(float));
    cudaMemsetAsync(tok_ptr, 0, (size_t)NUM_SP * EMBED * sizeof(int));
    k_prep_w<<<32, 256>>>(W1, W2, (const int*)msk);
    k_main<<<GRID_MAIN, 768, SMEM_TOTAL>>>(x, idx10, b1, b2);
    k_scatter<<<NUM_SP, 64>>>(idx21, msk, out);
}